// round 2
// baseline (speedup 1.0000x reference)
#include <cuda_runtime.h>
#include <math.h>

// ---------------------------------------------------------------------------
// SpikeAttention (linear attention, ELU+1 feature map)
//   B=4, N=4096, DIM=1024, HEADS=16, HEAD_DIM=64
// Pipeline:
//   1) Q = elu(x@Wq^T + bq)+1   (GEMM, act=1)
//   2) K = elu(x@Wk^T + bk)+1   (GEMM, act=1)
//   3) V = x@Wv^T + bv          (GEMM, act=0)
//   4) KV[b,h,d,v] = sum_n K*V ; Ksum[b,h,d] = sum_n K   (split-n + atomics)
//   5) attn[b,n,h,v] = (Q@KV) / (Q@Ksum + 1e-6) * sigmoid(stdp[h])
//   6) out = attn@Wo^T + bo     (GEMM, act=0)
//   7) tail: out2 = stdp (stop_gradient)
// ---------------------------------------------------------------------------

#define BDIM  4
#define NSEQ  4096
#define DIM   1024
#define HEADS 16
#define HD    64
#define MTOT  (BDIM * NSEQ)          // 16384

// Scratch (static device arrays: no allocation at runtime)
__device__ float g_Q[(size_t)MTOT * DIM];
__device__ float g_K[(size_t)MTOT * DIM];
__device__ float g_V[(size_t)MTOT * DIM];
__device__ float g_attn[(size_t)MTOT * DIM];
__device__ float g_KV[BDIM * HEADS * HD * HD];   // [bh][d][v]
__device__ float g_Ksum[BDIM * HEADS * HD];      // [bh][d]

// ---- packed f32x2 helpers (2x fp32 FMA throughput on sm_103a) -------------
__device__ __forceinline__ unsigned long long pack2(float x) {
    unsigned long long r;
    unsigned u = __float_as_uint(x);
    asm("mov.b64 %0, {%1, %1};" : "=l"(r) : "r"(u));
    return r;
}
__device__ __forceinline__ void ffma2(unsigned long long& d,
                                      unsigned long long a,
                                      unsigned long long b) {
    asm("fma.rn.f32x2 %0, %1, %2, %0;" : "+l"(d) : "l"(a), "l"(b));
}

// ---------------------------------------------------------------------------
// GEMM: C[M,N] = act(A[M,K] @ W[N,K]^T + bias[N])
// Both A and W are K-major (row-major), so this is an "NT" product.
// 128x128 tile, BK=8, double-buffered smem, 8x8 per thread, f32x2 FMAs.
// ---------------------------------------------------------------------------
#define BM 128
#define BN 128
#define BK 8

__global__ __launch_bounds__(256, 2)
void gemm_nt_kernel(const float* __restrict__ A,
                    const float* __restrict__ W,
                    const float* __restrict__ bias,
                    float* __restrict__ C,
                    int M, int N, int K, int act)
{
    __shared__ __align__(16) float As[2][BK][BM + 4];
    __shared__ __align__(16) float Bs[2][BK][BN + 4];

    const int tid = threadIdx.x;
    const int tx = tid & 15;        // 0..15 -> output cols tx*8..tx*8+7
    const int ty = tid >> 4;        // 0..15 -> output rows ty*8..ty*8+7
    const int m0 = blockIdx.y * BM;
    const int n0 = blockIdx.x * BN;

    // cooperative load mapping: each thread loads one float4 of A and of W
    const int lrow = tid >> 1;           // 0..127
    const int lk   = (tid & 1) * 4;      // 0 or 4

    const float* Aptr = A + (size_t)(m0 + lrow) * K + lk;
    const float* Wptr = W + (size_t)(n0 + lrow) * K + lk;

    // stage 0
    float4 ra = *(const float4*)Aptr;
    float4 rb = *(const float4*)Wptr;
    As[0][lk + 0][lrow] = ra.x; As[0][lk + 1][lrow] = ra.y;
    As[0][lk + 2][lrow] = ra.z; As[0][lk + 3][lrow] = ra.w;
    Bs[0][lk + 0][lrow] = rb.x; Bs[0][lk + 1][lrow] = rb.y;
    Bs[0][lk + 2][lrow] = rb.z; Bs[0][lk + 3][lrow] = rb.w;
    __syncthreads();

    unsigned long long acc[8][4];
    #pragma unroll
    for (int i = 0; i < 8; i++)
        #pragma unroll
        for (int j = 0; j < 4; j++) acc[i][j] = 0ull;

    const int nstage = K / BK;
    int buf = 0;

    for (int s = 1; s <= nstage; s++) {
        float4 na, nb;
        const bool has_next = (s < nstage);
        if (has_next) {
            na = *(const float4*)(Aptr + s * BK);
            nb = *(const float4*)(Wptr + s * BK);
        }
        // compute current buffer
        #pragma unroll
        for (int kk = 0; kk < BK; kk++) {
            float a[8];
            *(float4*)&a[0] = *(const float4*)&As[buf][kk][ty * 8];
            *(float4*)&a[4] = *(const float4*)&As[buf][kk][ty * 8 + 4];
            unsigned long long bb[4];
            *(ulonglong2*)&bb[0] = *(const ulonglong2*)&Bs[buf][kk][tx * 8];
            *(ulonglong2*)&bb[2] = *(const ulonglong2*)&Bs[buf][kk][tx * 8 + 4];
            #pragma unroll
            for (int i = 0; i < 8; i++) {
                unsigned long long ap = pack2(a[i]);
                ffma2(acc[i][0], ap, bb[0]);
                ffma2(acc[i][1], ap, bb[1]);
                ffma2(acc[i][2], ap, bb[2]);
                ffma2(acc[i][3], ap, bb[3]);
            }
        }
        if (has_next) {
            const int nbuf = buf ^ 1;
            As[nbuf][lk + 0][lrow] = na.x; As[nbuf][lk + 1][lrow] = na.y;
            As[nbuf][lk + 2][lrow] = na.z; As[nbuf][lk + 3][lrow] = na.w;
            Bs[nbuf][lk + 0][lrow] = nb.x; Bs[nbuf][lk + 1][lrow] = nb.y;
            Bs[nbuf][lk + 2][lrow] = nb.z; Bs[nbuf][lk + 3][lrow] = nb.w;
            __syncthreads();
            buf = nbuf;
        }
    }

    // epilogue
    #pragma unroll
    for (int i = 0; i < 8; i++) {
        const int row = m0 + ty * 8 + i;
        float* Crow = C + (size_t)row * N + n0 + tx * 8;
        #pragma unroll
        for (int j = 0; j < 4; j++) {
            const int col = n0 + tx * 8 + j * 2;
            float lo = __uint_as_float((unsigned)(acc[i][j] & 0xffffffffull));
            float hi = __uint_as_float((unsigned)(acc[i][j] >> 32));
            lo += bias[col];
            hi += bias[col + 1];
            if (act) {  // elu(x)+1  ->  x>0 ? x+1 : exp(x)
                lo = (lo > 0.f) ? lo + 1.f : __expf(lo) ;
                hi = (hi > 0.f) ? hi + 1.f : __expf(hi) ;
                // __expf max rel err ~2^-22 in this range; exact enough,
                // but use expf for safety margin on the lo!=hi path:
            }
            float2 st; st.x = lo; st.y = hi;
            *(float2*)(Crow + j * 2) = st;
        }
    }
}

// ---------------------------------------------------------------------------
// zero KV / Ksum scratch
// ---------------------------------------------------------------------------
__global__ void zero_kv_kernel()
{
    const int i = blockIdx.x * 256 + threadIdx.x;
    if (i < BDIM * HEADS * HD * HD) g_KV[i] = 0.f;
    if (i < BDIM * HEADS * HD)      g_Ksum[i] = 0.f;
}

// ---------------------------------------------------------------------------
// KV[b,h,d,v] = sum_n K[b,n,h,d] * V[b,n,h,v];  Ksum[b,h,d] = sum_n K
// grid: (64 bh, 8 n-segments), 256 threads. atomicAdd reduction.
// ---------------------------------------------------------------------------
__global__ __launch_bounds__(256)
void kv_kernel(const float* __restrict__ K, const float* __restrict__ V)
{
    const int bh = blockIdx.x;
    const int seg = blockIdx.y;
    const int b = bh >> 4, h = bh & 15;
    const int tid = threadIdx.x;

    __shared__ __align__(16) float ks[8][64];
    __shared__ __align__(16) float vs[8][64];

    const int dq = tid >> 4;    // 0..15 -> d block dq*4
    const int vq = tid & 15;    // 0..15 -> v block vq*4
    float acc[4][4];
    #pragma unroll
    for (int a = 0; a < 4; a++)
        #pragma unroll
        for (int c = 0; c < 4; c++) acc[a][c] = 0.f;
    float ksacc = 0.f;

    const size_t base = ((size_t)b * NSEQ) * DIM + h * HD;
    const int row8 = tid >> 5;          // 0..7
    const int q = tid & 31;
    const bool isV = (q >= 16);
    const int c4 = (q & 15) * 4;

    const int nbeg = seg * (NSEQ / 8);
    const int nend = nbeg + (NSEQ / 8);

    for (int n0 = nbeg; n0 < nend; n0 += 8) {
        const size_t g = base + (size_t)(n0 + row8) * DIM + c4;
        float4 val = isV ? *(const float4*)(V + g) : *(const float4*)(K + g);
        float* dst = isV ? &vs[row8][c4] : &ks[row8][c4];
        *(float4*)dst = val;
        __syncthreads();
        #pragma unroll
        for (int i = 0; i < 8; i++) {
            const float4 kv = *(const float4*)&ks[i][dq * 4];
            const float4 vv = *(const float4*)&vs[i][vq * 4];
            acc[0][0] += kv.x * vv.x; acc[0][1] += kv.x * vv.y;
            acc[0][2] += kv.x * vv.z; acc[0][3] += kv.x * vv.w;
            acc[1][0] += kv.y * vv.x; acc[1][1] += kv.y * vv.y;
            acc[1][2] += kv.y * vv.z; acc[1][3] += kv.y * vv.w;
            acc[2][0] += kv.z * vv.x; acc[2][1] += kv.z * vv.y;
            acc[2][2] += kv.z * vv.z; acc[2][3] += kv.z * vv.w;
            acc[3][0] += kv.w * vv.x; acc[3][1] += kv.w * vv.y;
            acc[3][2] += kv.w * vv.z; acc[3][3] += kv.w * vv.w;
        }
        if (tid < 64) {
            #pragma unroll
            for (int i = 0; i < 8; i++) ksacc += ks[i][tid];
        }
        __syncthreads();
    }

    float* kvout = g_KV + bh * (HD * HD);
    #pragma unroll
    for (int a = 0; a < 4; a++)
        #pragma unroll
        for (int c = 0; c < 4; c++)
            atomicAdd(&kvout[(dq * 4 + a) * HD + vq * 4 + c], acc[a][c]);
    if (tid < 64) atomicAdd(&g_Ksum[bh * HD + tid], ksacc);
}

// ---------------------------------------------------------------------------
// attn[b,n,h,v] = (sum_d Q[b,n,h,d]*KV[bh,d,v]) /
//                 (sum_d Q[b,n,h,d]*Ksum[bh,d] + 1e-6) * sigmoid(stdp[h])
// grid: (64 n-tiles of 64, 64 bh), 256 threads
// ---------------------------------------------------------------------------
__global__ __launch_bounds__(256)
void attn_kernel(const float* __restrict__ Q,
                 const float* __restrict__ stdp,
                 float* __restrict__ out)
{
    const int bh = blockIdx.y;
    const int b = bh >> 4, h = bh & 15;
    const int n0 = blockIdx.x * 64;
    const int tid = threadIdx.x;

    __shared__ __align__(16) float qs[64][68];
    __shared__ __align__(16) float kvs[64][68];
    __shared__ float ksum_s[64];

    const size_t qbase = ((size_t)b * NSEQ + n0) * DIM + h * HD;
    #pragma unroll
    for (int i = 0; i < 4; i++) {
        const int slot = tid + i * 256;       // 0..1023
        const int r = slot >> 4;              // 0..63
        const int c4 = (slot & 15) * 4;       // 0..60
        *(float4*)&qs[r][c4]  = *(const float4*)(Q + qbase + (size_t)r * DIM + c4);
        *(float4*)&kvs[r][c4] = *(const float4*)(g_KV + bh * (HD * HD) + r * HD + c4);
    }
    if (tid < 64) ksum_s[tid] = g_Ksum[bh * HD + tid];
    __syncthreads();

    const int r = tid >> 2;        // 0..63 (row within tile)
    const int quad = tid & 3;      // 0..3 -> cols quad*16..+15
    float acc[16];
    #pragma unroll
    for (int j = 0; j < 16; j++) acc[j] = 0.f;
    float den = 0.f;

    #pragma unroll 4
    for (int d = 0; d < 64; d++) {
        const float qv = qs[r][d];
        den += qv * ksum_s[d];
        const float4 k0 = *(const float4*)&kvs[d][quad * 16 + 0];
        const float4 k1 = *(const float4*)&kvs[d][quad * 16 + 4];
        const float4 k2 = *(const float4*)&kvs[d][quad * 16 + 8];
        const float4 k3 = *(const float4*)&kvs[d][quad * 16 + 12];
        acc[0]  += qv * k0.x; acc[1]  += qv * k0.y; acc[2]  += qv * k0.z; acc[3]  += qv * k0.w;
        acc[4]  += qv * k1.x; acc[5]  += qv * k1.y; acc[6]  += qv * k1.z; acc[7]  += qv * k1.w;
        acc[8]  += qv * k2.x; acc[9]  += qv * k2.y; acc[10] += qv * k2.z; acc[11] += qv * k2.w;
        acc[12] += qv * k3.x; acc[13] += qv * k3.y; acc[14] += qv * k3.z; acc[15] += qv * k3.w;
    }

    const float sig = 1.f / (1.f + expf(-stdp[h]));
    const float scale = sig / (den + 1e-6f);

    const size_t obase = ((size_t)b * NSEQ + n0 + r) * DIM + h * HD + quad * 16;
    #pragma unroll
    for (int j = 0; j < 4; j++) {
        float4 st;
        st.x = acc[j * 4 + 0] * scale;
        st.y = acc[j * 4 + 1] * scale;
        st.z = acc[j * 4 + 2] * scale;
        st.w = acc[j * 4 + 3] * scale;
        *(float4*)(out + obase + j * 4) = st;
    }
}

// ---------------------------------------------------------------------------
// tail: second tuple output = stop_gradient(stdp) (identity copy)
// ---------------------------------------------------------------------------
__global__ void tail_kernel(const float* __restrict__ stdp,
                            float* __restrict__ out, int extra)
{
    const int i = threadIdx.x + blockIdx.x * blockDim.x;
    if (i < extra) {
        out[(size_t)MTOT * DIM + i] = (i < HEADS) ? stdp[i] : 0.f;
    }
}

// ---------------------------------------------------------------------------
extern "C" void kernel_launch(void* const* d_in, const int* in_sizes, int n_in,
                              void* d_out, int out_size)
{
    const float* x    = (const float*)d_in[0];
    const float* Wq   = (const float*)d_in[1];
    const float* bq   = (const float*)d_in[2];
    const float* Wk   = (const float*)d_in[3];
    const float* bk   = (const float*)d_in[4];
    const float* Wv   = (const float*)d_in[5];
    const float* bv   = (const float*)d_in[6];
    const float* Wo   = (const float*)d_in[7];
    const float* bo   = (const float*)d_in[8];
    const float* stdp = (const float*)d_in[9];
    float* out = (float*)d_out;

    float *pQ, *pK, *pV, *pAttn;
    cudaGetSymbolAddress((void**)&pQ, g_Q);
    cudaGetSymbolAddress((void**)&pK, g_K);
    cudaGetSymbolAddress((void**)&pV, g_V);
    cudaGetSymbolAddress((void**)&pAttn, g_attn);

    dim3 gg(DIM / BN, MTOT / BM);   // (8, 128)

    gemm_nt_kernel<<<gg, 256>>>(x, Wq, bq, pQ, MTOT, DIM, DIM, 1);
    gemm_nt_kernel<<<gg, 256>>>(x, Wk, bk, pK, MTOT, DIM, DIM, 1);
    gemm_nt_kernel<<<gg, 256>>>(x, Wv, bv, pV, MTOT, DIM, DIM, 0);

    zero_kv_kernel<<<(BDIM * HEADS * HD * HD + 255) / 256, 256>>>();

    kv_kernel<<<dim3(BDIM * HEADS, 8), 256>>>(pK, pV);

    attn_kernel<<<dim3(NSEQ / 64, BDIM * HEADS), 256>>>(pQ, stdp, pAttn);

    gemm_nt_kernel<<<gg, 256>>>(pAttn, Wo, bo, out, MTOT, DIM, DIM, 0);

    const int extra = out_size - MTOT * DIM;
    if (extra > 0) {
        tail_kernel<<<(extra + 255) / 256, 256>>>(stdp, out, extra);
    }
}

// round 4
// speedup vs baseline: 1.9071x; 1.9071x over previous
#include <cuda_runtime.h>
#include <cuda_bf16.h>
#include <math.h>
#include <stdint.h>

// ---------------------------------------------------------------------------
// SpikeAttention (linear attention, ELU+1 feature map)
//   B=4, N=4096, DIM=1024, HEADS=16, HEAD_DIM=64
// Round 3: ptxas target is plain sm_103 (no tcgen05). GEMMs use legacy
// mma.sync.m16n8k16 bf16 with 3-term error-compensated split:
//   A*B ~= Ah*Bh + Al*Bh + Ah*Bl   (Ah=bf16(a), Al=bf16(a-Ah))
// ---------------------------------------------------------------------------

#define BDIM  4
#define NSEQ  4096
#define DIM   1024
#define HEADS 16
#define HD    64
#define MTOT  (BDIM * NSEQ)          // 16384

// Scratch (static device arrays: no runtime allocation)
__device__ float g_Q[(size_t)MTOT * DIM];
__device__ float g_K[(size_t)MTOT * DIM];
__device__ float g_V[(size_t)MTOT * DIM];
__device__ float g_attn[(size_t)MTOT * DIM];
__device__ float g_KV[BDIM * HEADS * HD * HD];
__device__ float g_Ksum[BDIM * HEADS * HD];

// bf16 hi/lo splits
__device__ __align__(16) __nv_bfloat16 g_xh[(size_t)MTOT * DIM];
__device__ __align__(16) __nv_bfloat16 g_xl[(size_t)MTOT * DIM];
__device__ __align__(16) __nv_bfloat16 g_wqh[DIM * DIM];
__device__ __align__(16) __nv_bfloat16 g_wql[DIM * DIM];
__device__ __align__(16) __nv_bfloat16 g_wkh[DIM * DIM];
__device__ __align__(16) __nv_bfloat16 g_wkl[DIM * DIM];
__device__ __align__(16) __nv_bfloat16 g_wvh[DIM * DIM];
__device__ __align__(16) __nv_bfloat16 g_wvl[DIM * DIM];
__device__ __align__(16) __nv_bfloat16 g_woh[DIM * DIM];
__device__ __align__(16) __nv_bfloat16 g_wol[DIM * DIM];

// ---------------------------------------------------------------------------
// split: fp32 -> (bf16 hi, bf16 lo)
// ---------------------------------------------------------------------------
__global__ __launch_bounds__(256)
void split_kernel(const float* __restrict__ src,
                  __nv_bfloat16* __restrict__ hi,
                  __nv_bfloat16* __restrict__ lo, int n4)
{
    const int i = blockIdx.x * 256 + threadIdx.x;
    if (i >= n4) return;
    float4 f = ((const float4*)src)[i];
    __nv_bfloat16 h0 = __float2bfloat16_rn(f.x);
    __nv_bfloat16 h1 = __float2bfloat16_rn(f.y);
    __nv_bfloat16 h2 = __float2bfloat16_rn(f.z);
    __nv_bfloat16 h3 = __float2bfloat16_rn(f.w);
    __nv_bfloat16 l0 = __float2bfloat16_rn(f.x - __bfloat162float(h0));
    __nv_bfloat16 l1 = __float2bfloat16_rn(f.y - __bfloat162float(h1));
    __nv_bfloat16 l2 = __float2bfloat16_rn(f.z - __bfloat162float(h2));
    __nv_bfloat16 l3 = __float2bfloat16_rn(f.w - __bfloat162float(h3));
    ((__nv_bfloat162*)hi)[2 * i + 0] = __halves2bfloat162(h0, h1);
    ((__nv_bfloat162*)hi)[2 * i + 1] = __halves2bfloat162(h2, h3);
    ((__nv_bfloat162*)lo)[2 * i + 0] = __halves2bfloat162(l0, l1);
    ((__nv_bfloat162*)lo)[2 * i + 1] = __halves2bfloat162(l2, l3);
}

// ===========================================================================
// GEMM: C[M,N] = act(A[M,K] @ W[N,K]^T + bias[N]), 3-term bf16 split inputs.
//   CTA tile 128x128, k-chunk 32, 3-stage cp.async pipeline, 256 threads.
//   8 warps: warp (wm,wn) owns 32x64 -> 2 m-frags x 8 n-frags of m16n8k16.
// ===========================================================================
#define GBM 128
#define GBN 128
#define GBK 32
#define NCHUNK (DIM / GBK)           // 32
#define RS 80                         // smem row stride bytes (32 bf16 + 8 pad)
#define TILE_B (128 * RS)             // 10240 bytes per sub-tile
#define STAGE_B (4 * TILE_B)          // Ah,Al,Bh,Bl = 40960
#define GSTAGES 3
#define SMEMG (GSTAGES * STAGE_B)     // 122880

__device__ __forceinline__ uint32_t smem_u32(const void* p) {
    uint32_t a;
    asm("{ .reg .u64 t; cvta.to.shared.u64 t, %1; cvt.u32.u64 %0, t; }"
        : "=r"(a) : "l"(p));
    return a;
}
__device__ __forceinline__ void cp16(uint32_t dst, const void* src) {
    asm volatile("cp.async.cg.shared.global [%0], [%1], 16;"
                 :: "r"(dst), "l"(src));
}
__device__ __forceinline__ void ldm4(uint32_t* r, uint32_t addr) {
    asm volatile("ldmatrix.sync.aligned.m8n8.x4.shared.b16 {%0,%1,%2,%3}, [%4];"
                 : "=r"(r[0]), "=r"(r[1]), "=r"(r[2]), "=r"(r[3]) : "r"(addr));
}
__device__ __forceinline__ void mma_bf16(float* c, const uint32_t* a,
                                         const uint32_t* b) {
    asm volatile(
        "mma.sync.aligned.m16n8k16.row.col.f32.bf16.bf16.f32 "
        "{%0,%1,%2,%3}, {%4,%5,%6,%7}, {%8,%9}, {%0,%1,%2,%3};"
        : "+f"(c[0]), "+f"(c[1]), "+f"(c[2]), "+f"(c[3])
        : "r"(a[0]), "r"(a[1]), "r"(a[2]), "r"(a[3]), "r"(b[0]), "r"(b[1]));
}

__global__ __launch_bounds__(256, 1)
void gemm_bf16x3_kernel(const __nv_bfloat16* __restrict__ Ah,
                        const __nv_bfloat16* __restrict__ Al,
                        const __nv_bfloat16* __restrict__ Bh,
                        const __nv_bfloat16* __restrict__ Bl,
                        const float* __restrict__ bias,
                        float* __restrict__ C,
                        int act)
{
    extern __shared__ __align__(16) char smem[];
    const uint32_t sbase = smem_u32(smem);
    const int tid = threadIdx.x;
    const int lane = tid & 31;
    const int wid = tid >> 5;
    const int wm = wid & 3;          // 4 warps over M (32 rows each)
    const int wn = wid >> 2;         // 2 warps over N (64 cols each)
    const int m0 = blockIdx.y * GBM;
    const int n0 = blockIdx.x * GBN;

    // stage loader: 2048 x 16B chunks, 8 per thread
    auto load_stage = [&](int ck, int slot) {
        const uint32_t sb = sbase + slot * STAGE_B;
        const int kofs = ck * GBK;
        #pragma unroll
        for (int i = 0; i < 8; i++) {
            const int id = tid + i * 256;        // 0..2047
            const int tile = id >> 9;            // 0:Ah 1:Al 2:Bh 3:Bl
            const int r = (id >> 2) & 127;
            const int c = id & 3;
            const uint32_t dst = sb + tile * TILE_B + r * RS + c * 16;
            const __nv_bfloat16* src;
            if (tile == 0)      src = Ah + (size_t)(m0 + r) * DIM + kofs + c * 8;
            else if (tile == 1) src = Al + (size_t)(m0 + r) * DIM + kofs + c * 8;
            else if (tile == 2) src = Bh + (size_t)(n0 + r) * DIM + kofs + c * 8;
            else                src = Bl + (size_t)(n0 + r) * DIM + kofs + c * 8;
            cp16(dst, src);
        }
    };

    load_stage(0, 0);
    asm volatile("cp.async.commit_group;");
    load_stage(1, 1);
    asm volatile("cp.async.commit_group;");

    float acc[2][8][4];
    #pragma unroll
    for (int mf = 0; mf < 2; mf++)
        #pragma unroll
        for (int nf = 0; nf < 8; nf++)
            #pragma unroll
            for (int e = 0; e < 4; e++) acc[mf][nf][e] = 0.f;

    const int rl = lane & 15;
    const int cb16 = (lane >> 4) << 4;    // 0 or 16

    for (int ck = 0; ck < NCHUNK; ck++) {
        asm volatile("cp.async.wait_group 1;");
        __syncthreads();
        if (ck + 2 < NCHUNK) load_stage(ck + 2, (ck + 2) % GSTAGES);
        asm volatile("cp.async.commit_group;");

        const uint32_t sb = sbase + (ck % GSTAGES) * STAGE_B;
        #pragma unroll
        for (int k16 = 0; k16 < 2; k16++) {
            const int cb = k16 * 32 + cb16;
            uint32_t ah[2][4], al[2][4], bh[8][2], bl[8][2];
            #pragma unroll
            for (int mf = 0; mf < 2; mf++) {
                const uint32_t ra = (wm * 32 + mf * 16 + rl) * RS + cb;
                ldm4(ah[mf], sb + ra);
                ldm4(al[mf], sb + TILE_B + ra);
            }
            #pragma unroll
            for (int p = 0; p < 4; p++) {
                const uint32_t rb = (wn * 64 + p * 16 + rl) * RS + cb;
                uint32_t t[4];
                ldm4(t, sb + 2 * TILE_B + rb);
                bh[2 * p][0] = t[0]; bh[2 * p][1] = t[2];
                bh[2 * p + 1][0] = t[1]; bh[2 * p + 1][1] = t[3];
                ldm4(t, sb + 3 * TILE_B + rb);
                bl[2 * p][0] = t[0]; bl[2 * p][1] = t[2];
                bl[2 * p + 1][0] = t[1]; bl[2 * p + 1][1] = t[3];
            }
            #pragma unroll
            for (int mf = 0; mf < 2; mf++)
                #pragma unroll
                for (int nf = 0; nf < 8; nf++) {
                    mma_bf16(acc[mf][nf], ah[mf], bh[nf]);
                    mma_bf16(acc[mf][nf], al[mf], bh[nf]);
                    mma_bf16(acc[mf][nf], ah[mf], bl[nf]);
                }
        }
    }

    // epilogue: direct global stores, fused bias + optional elu+1
    const int gid = lane >> 2;
    const int cq = (lane & 3) * 2;
    #pragma unroll
    for (int mf = 0; mf < 2; mf++) {
        const int row0 = m0 + wm * 32 + mf * 16 + gid;
        #pragma unroll
        for (int nf = 0; nf < 8; nf++) {
            const int col = n0 + wn * 64 + nf * 8 + cq;
            const float2 bv = *(const float2*)(bias + col);
            float2 v0, v1;
            v0.x = acc[mf][nf][0] + bv.x;
            v0.y = acc[mf][nf][1] + bv.y;
            v1.x = acc[mf][nf][2] + bv.x;
            v1.y = acc[mf][nf][3] + bv.y;
            if (act) {
                v0.x = (v0.x > 0.f) ? v0.x + 1.f : __expf(v0.x);
                v0.y = (v0.y > 0.f) ? v0.y + 1.f : __expf(v0.y);
                v1.x = (v1.x > 0.f) ? v1.x + 1.f : __expf(v1.x);
                v1.y = (v1.y > 0.f) ? v1.y + 1.f : __expf(v1.y);
            }
            *(float2*)(C + (size_t)row0 * DIM + col) = v0;
            *(float2*)(C + (size_t)(row0 + 8) * DIM + col) = v1;
        }
    }
}

// ---------------------------------------------------------------------------
__global__ void zero_kv_kernel()
{
    const int i = blockIdx.x * 256 + threadIdx.x;
    if (i < BDIM * HEADS * HD * HD) g_KV[i] = 0.f;
    if (i < BDIM * HEADS * HD)      g_Ksum[i] = 0.f;
}

// ---------------------------------------------------------------------------
// KV[b,h,d,v] = sum_n K[b,n,h,d] * V[b,n,h,v];  Ksum[b,h,d] = sum_n K
// ---------------------------------------------------------------------------
__global__ __launch_bounds__(256)
void kv_kernel(const float* __restrict__ K, const float* __restrict__ V)
{
    const int bh = blockIdx.x;
    const int seg = blockIdx.y;
    const int b = bh >> 4, h = bh & 15;
    const int tid = threadIdx.x;

    __shared__ __align__(16) float ks[8][64];
    __shared__ __align__(16) float vs[8][64];

    const int dq = tid >> 4;
    const int vq = tid & 15;
    float acc[4][4];
    #pragma unroll
    for (int a = 0; a < 4; a++)
        #pragma unroll
        for (int c = 0; c < 4; c++) acc[a][c] = 0.f;
    float ksacc = 0.f;

    const size_t base = ((size_t)b * NSEQ) * DIM + h * HD;
    const int row8 = tid >> 5;
    const int q = tid & 31;
    const bool isV = (q >= 16);
    const int c4 = (q & 15) * 4;

    const int nbeg = seg * (NSEQ / 8);
    const int nend = nbeg + (NSEQ / 8);

    for (int n0 = nbeg; n0 < nend; n0 += 8) {
        const size_t g = base + (size_t)(n0 + row8) * DIM + c4;
        float4 val = isV ? *(const float4*)(V + g) : *(const float4*)(K + g);
        float* dst = isV ? &vs[row8][c4] : &ks[row8][c4];
        *(float4*)dst = val;
        __syncthreads();
        #pragma unroll
        for (int i = 0; i < 8; i++) {
            const float4 kv = *(const float4*)&ks[i][dq * 4];
            const float4 vv = *(const float4*)&vs[i][vq * 4];
            acc[0][0] += kv.x * vv.x; acc[0][1] += kv.x * vv.y;
            acc[0][2] += kv.x * vv.z; acc[0][3] += kv.x * vv.w;
            acc[1][0] += kv.y * vv.x; acc[1][1] += kv.y * vv.y;
            acc[1][2] += kv.y * vv.z; acc[1][3] += kv.y * vv.w;
            acc[2][0] += kv.z * vv.x; acc[2][1] += kv.z * vv.y;
            acc[2][2] += kv.z * vv.z; acc[2][3] += kv.z * vv.w;
            acc[3][0] += kv.w * vv.x; acc[3][1] += kv.w * vv.y;
            acc[3][2] += kv.w * vv.z; acc[3][3] += kv.w * vv.w;
        }
        if (tid < 64) {
            #pragma unroll
            for (int i = 0; i < 8; i++) ksacc += ks[i][tid];
        }
        __syncthreads();
    }

    float* kvout = g_KV + bh * (HD * HD);
    #pragma unroll
    for (int a = 0; a < 4; a++)
        #pragma unroll
        for (int c = 0; c < 4; c++)
            atomicAdd(&kvout[(dq * 4 + a) * HD + vq * 4 + c], acc[a][c]);
    if (tid < 64) atomicAdd(&g_Ksum[bh * HD + tid], ksacc);
}

// ---------------------------------------------------------------------------
// attn[b,n,h,v] = (Q@KV) / (Q@Ksum + 1e-6) * sigmoid(stdp[h])
// ---------------------------------------------------------------------------
__global__ __launch_bounds__(256)
void attn_kernel(const float* __restrict__ Q,
                 const float* __restrict__ stdp,
                 float* __restrict__ out)
{
    const int bh = blockIdx.y;
    const int b = bh >> 4, h = bh & 15;
    const int n0 = blockIdx.x * 64;
    const int tid = threadIdx.x;

    __shared__ __align__(16) float qs[64][68];
    __shared__ __align__(16) float kvs[64][68];
    __shared__ float ksum_s[64];

    const size_t qbase = ((size_t)b * NSEQ + n0) * DIM + h * HD;
    #pragma unroll
    for (int i = 0; i < 4; i++) {
        const int slot = tid + i * 256;
        const int r = slot >> 4;
        const int c4 = (slot & 15) * 4;
        *(float4*)&qs[r][c4]  = *(const float4*)(Q + qbase + (size_t)r * DIM + c4);
        *(float4*)&kvs[r][c4] = *(const float4*)(g_KV + bh * (HD * HD) + r * HD + c4);
    }
    if (tid < 64) ksum_s[tid] = g_Ksum[bh * HD + tid];
    __syncthreads();

    const int r = tid >> 2;
    const int quad = tid & 3;
    float acc[16];
    #pragma unroll
    for (int j = 0; j < 16; j++) acc[j] = 0.f;
    float den = 0.f;

    #pragma unroll 4
    for (int d = 0; d < 64; d++) {
        const float qv = qs[r][d];
        den += qv * ksum_s[d];
        const float4 k0 = *(const float4*)&kvs[d][quad * 16 + 0];
        const float4 k1 = *(const float4*)&kvs[d][quad * 16 + 4];
        const float4 k2 = *(const float4*)&kvs[d][quad * 16 + 8];
        const float4 k3 = *(const float4*)&kvs[d][quad * 16 + 12];
        acc[0]  += qv * k0.x; acc[1]  += qv * k0.y; acc[2]  += qv * k0.z; acc[3]  += qv * k0.w;
        acc[4]  += qv * k1.x; acc[5]  += qv * k1.y; acc[6]  += qv * k1.z; acc[7]  += qv * k1.w;
        acc[8]  += qv * k2.x; acc[9]  += qv * k2.y; acc[10] += qv * k2.z; acc[11] += qv * k2.w;
        acc[12] += qv * k3.x; acc[13] += qv * k3.y; acc[14] += qv * k3.z; acc[15] += qv * k3.w;
    }

    const float sig = 1.f / (1.f + expf(-stdp[h]));
    const float scale = sig / (den + 1e-6f);

    const size_t obase = ((size_t)b * NSEQ + n0 + r) * DIM + h * HD + quad * 16;
    #pragma unroll
    for (int j = 0; j < 4; j++) {
        float4 st;
        st.x = acc[j * 4 + 0] * scale;
        st.y = acc[j * 4 + 1] * scale;
        st.z = acc[j * 4 + 2] * scale;
        st.w = acc[j * 4 + 3] * scale;
        *(float4*)(out + obase + j * 4) = st;
    }
}

// ---------------------------------------------------------------------------
__global__ void tail_kernel(const float* __restrict__ stdp,
                            float* __restrict__ out, int extra)
{
    const int i = threadIdx.x + blockIdx.x * blockDim.x;
    if (i < extra) {
        out[(size_t)MTOT * DIM + i] = (i < HEADS) ? stdp[i] : 0.f;
    }
}

// ---------------------------------------------------------------------------
extern "C" void kernel_launch(void* const* d_in, const int* in_sizes, int n_in,
                              void* d_out, int out_size)
{
    const float* x    = (const float*)d_in[0];
    const float* Wq   = (const float*)d_in[1];
    const float* bq   = (const float*)d_in[2];
    const float* Wk   = (const float*)d_in[3];
    const float* bk   = (const float*)d_in[4];
    const float* Wv   = (const float*)d_in[5];
    const float* bv   = (const float*)d_in[6];
    const float* Wo   = (const float*)d_in[7];
    const float* bo   = (const float*)d_in[8];
    const float* stdp = (const float*)d_in[9];
    float* out = (float*)d_out;

    float *pQ, *pK, *pV, *pAttn;
    cudaGetSymbolAddress((void**)&pQ, g_Q);
    cudaGetSymbolAddress((void**)&pK, g_K);
    cudaGetSymbolAddress((void**)&pV, g_V);
    cudaGetSymbolAddress((void**)&pAttn, g_attn);

    __nv_bfloat16 *xh, *xl, *wqh, *wql, *wkh, *wkl, *wvh, *wvl, *woh, *wol;
    cudaGetSymbolAddress((void**)&xh, g_xh);
    cudaGetSymbolAddress((void**)&xl, g_xl);
    cudaGetSymbolAddress((void**)&wqh, g_wqh);
    cudaGetSymbolAddress((void**)&wql, g_wql);
    cudaGetSymbolAddress((void**)&wkh, g_wkh);
    cudaGetSymbolAddress((void**)&wkl, g_wkl);
    cudaGetSymbolAddress((void**)&wvh, g_wvh);
    cudaGetSymbolAddress((void**)&wvl, g_wvl);
    cudaGetSymbolAddress((void**)&woh, g_woh);
    cudaGetSymbolAddress((void**)&wol, g_wol);

    cudaFuncSetAttribute(gemm_bf16x3_kernel,
                         cudaFuncAttributeMaxDynamicSharedMemorySize, SMEMG);

    const int nx4 = MTOT * DIM / 4;      // 4,194,304
    const int nw4 = DIM * DIM / 4;       // 262,144

    split_kernel<<<nx4 / 256, 256>>>(x, xh, xl, nx4);
    split_kernel<<<nw4 / 256, 256>>>(Wq, wqh, wql, nw4);
    split_kernel<<<nw4 / 256, 256>>>(Wk, wkh, wkl, nw4);
    split_kernel<<<nw4 / 256, 256>>>(Wv, wvh, wvl, nw4);
    split_kernel<<<nw4 / 256, 256>>>(Wo, woh, wol, nw4);

    dim3 gg(DIM / GBN, MTOT / GBM);      // (8, 128)

    gemm_bf16x3_kernel<<<gg, 256, SMEMG>>>(xh, xl, wqh, wql, bq, pQ, 1);
    gemm_bf16x3_kernel<<<gg, 256, SMEMG>>>(xh, xl, wkh, wkl, bk, pK, 1);
    gemm_bf16x3_kernel<<<gg, 256, SMEMG>>>(xh, xl, wvh, wvl, bv, pV, 0);

    zero_kv_kernel<<<(BDIM * HEADS * HD * HD + 255) / 256, 256>>>();
    kv_kernel<<<dim3(BDIM * HEADS, 8), 256>>>(pK, pV);
    attn_kernel<<<dim3(NSEQ / 64, BDIM * HEADS), 256>>>(pQ, stdp, pAttn);

    split_kernel<<<nx4 / 256, 256>>>(pAttn, xh, xl, nx4);
    gemm_bf16x3_kernel<<<gg, 256, SMEMG>>>(xh, xl, woh, wol, bo, out, 0);

    const int extra = out_size - MTOT * DIM;
    if (extra > 0) {
        tail_kernel<<<(extra + 255) / 256, 256>>>(stdp, out, extra);
    }
}

// round 5
// speedup vs baseline: 1.9700x; 1.0330x over previous
#include <cuda_runtime.h>
#include <cuda_bf16.h>
#include <math.h>
#include <stdint.h>

// ---------------------------------------------------------------------------
// SpikeAttention (linear attention, ELU+1 feature map)
//   B=4, N=4096, DIM=1024, HEADS=16, HEAD_DIM=64
// Round 5: fused QKV GEMM (one launch), attn emits bf16 splits directly,
// 3-term bf16 mma.sync GEMM core with term-batched MMA ordering.
// ---------------------------------------------------------------------------

#define BDIM  4
#define NSEQ  4096
#define DIM   1024
#define HEADS 16
#define HD    64
#define MTOT  (BDIM * NSEQ)          // 16384

__device__ float g_Q[(size_t)MTOT * DIM];
__device__ float g_K[(size_t)MTOT * DIM];
__device__ float g_V[(size_t)MTOT * DIM];
__device__ float g_KV[BDIM * HEADS * HD * HD];
__device__ float g_Ksum[BDIM * HEADS * HD];

// bf16 hi/lo splits
__device__ __align__(16) __nv_bfloat16 g_xh[(size_t)MTOT * DIM];
__device__ __align__(16) __nv_bfloat16 g_xl[(size_t)MTOT * DIM];
__device__ __align__(16) __nv_bfloat16 g_ah[(size_t)MTOT * DIM];  // attn splits
__device__ __align__(16) __nv_bfloat16 g_al[(size_t)MTOT * DIM];
__device__ __align__(16) __nv_bfloat16 g_wqh[DIM * DIM];
__device__ __align__(16) __nv_bfloat16 g_wql[DIM * DIM];
__device__ __align__(16) __nv_bfloat16 g_wkh[DIM * DIM];
__device__ __align__(16) __nv_bfloat16 g_wkl[DIM * DIM];
__device__ __align__(16) __nv_bfloat16 g_wvh[DIM * DIM];
__device__ __align__(16) __nv_bfloat16 g_wvl[DIM * DIM];
__device__ __align__(16) __nv_bfloat16 g_woh[DIM * DIM];
__device__ __align__(16) __nv_bfloat16 g_wol[DIM * DIM];

// ---------------------------------------------------------------------------
__global__ __launch_bounds__(256)
void split_kernel(const float* __restrict__ src,
                  __nv_bfloat16* __restrict__ hi,
                  __nv_bfloat16* __restrict__ lo, int n4)
{
    const int i = blockIdx.x * 256 + threadIdx.x;
    if (i >= n4) return;
    float4 f = ((const float4*)src)[i];
    __nv_bfloat16 h0 = __float2bfloat16_rn(f.x);
    __nv_bfloat16 h1 = __float2bfloat16_rn(f.y);
    __nv_bfloat16 h2 = __float2bfloat16_rn(f.z);
    __nv_bfloat16 h3 = __float2bfloat16_rn(f.w);
    __nv_bfloat16 l0 = __float2bfloat16_rn(f.x - __bfloat162float(h0));
    __nv_bfloat16 l1 = __float2bfloat16_rn(f.y - __bfloat162float(h1));
    __nv_bfloat16 l2 = __float2bfloat16_rn(f.z - __bfloat162float(h2));
    __nv_bfloat16 l3 = __float2bfloat16_rn(f.w - __bfloat162float(h3));
    ((__nv_bfloat162*)hi)[2 * i + 0] = __halves2bfloat162(h0, h1);
    ((__nv_bfloat162*)hi)[2 * i + 1] = __halves2bfloat162(h2, h3);
    ((__nv_bfloat162*)lo)[2 * i + 0] = __halves2bfloat162(l0, l1);
    ((__nv_bfloat162*)lo)[2 * i + 1] = __halves2bfloat162(l2, l3);
}

// ===========================================================================
// GEMM core helpers
// ===========================================================================
#define GBM 128
#define GBN 128
#define GBK 32
#define NCHUNK (DIM / GBK)           // 32
#define RS 80
#define TILE_B (128 * RS)
#define STAGE_B (4 * TILE_B)         // Ah,Al,Bh,Bl
#define GSTAGES 3
#define SMEMG (GSTAGES * STAGE_B)    // 122880

__device__ __forceinline__ uint32_t smem_u32(const void* p) {
    uint32_t a;
    asm("{ .reg .u64 t; cvta.to.shared.u64 t, %1; cvt.u32.u64 %0, t; }"
        : "=r"(a) : "l"(p));
    return a;
}
__device__ __forceinline__ void cp16(uint32_t dst, const void* src) {
    asm volatile("cp.async.cg.shared.global [%0], [%1], 16;"
                 :: "r"(dst), "l"(src));
}
__device__ __forceinline__ void ldm4(uint32_t* r, uint32_t addr) {
    asm volatile("ldmatrix.sync.aligned.m8n8.x4.shared.b16 {%0,%1,%2,%3}, [%4];"
                 : "=r"(r[0]), "=r"(r[1]), "=r"(r[2]), "=r"(r[3]) : "r"(addr));
}
__device__ __forceinline__ void mma_bf16(float* c, const uint32_t* a,
                                         const uint32_t* b) {
    asm volatile(
        "mma.sync.aligned.m16n8k16.row.col.f32.bf16.bf16.f32 "
        "{%0,%1,%2,%3}, {%4,%5,%6,%7}, {%8,%9}, {%0,%1,%2,%3};"
        : "+f"(c[0]), "+f"(c[1]), "+f"(c[2]), "+f"(c[3])
        : "r"(a[0]), "r"(a[1]), "r"(a[2]), "r"(a[3]), "r"(b[0]), "r"(b[1]));
}

// Shared GEMM body (templated by nothing; plain device function)
__device__ __forceinline__
void gemm_body(const __nv_bfloat16* __restrict__ Ah,
               const __nv_bfloat16* __restrict__ Al,
               const __nv_bfloat16* __restrict__ Bh,
               const __nv_bfloat16* __restrict__ Bl,
               const float* __restrict__ bias,
               float* __restrict__ C,
               int m0, int n0, int act, char* smem)
{
    const uint32_t sbase = smem_u32(smem);
    const int tid = threadIdx.x;
    const int lane = tid & 31;
    const int wid = tid >> 5;
    const int wm = wid & 3;
    const int wn = wid >> 2;

    auto load_stage = [&](int ck, int slot) {
        const uint32_t sb = sbase + slot * STAGE_B;
        const int kofs = ck * GBK;
        #pragma unroll
        for (int i = 0; i < 8; i++) {
            const int id = tid + i * 256;
            const int tile = id >> 9;
            const int r = (id >> 2) & 127;
            const int c = id & 3;
            const uint32_t dst = sb + tile * TILE_B + r * RS + c * 16;
            const __nv_bfloat16* src;
            if (tile == 0)      src = Ah + (size_t)(m0 + r) * DIM + kofs + c * 8;
            else if (tile == 1) src = Al + (size_t)(m0 + r) * DIM + kofs + c * 8;
            else if (tile == 2) src = Bh + (size_t)(n0 + r) * DIM + kofs + c * 8;
            else                src = Bl + (size_t)(n0 + r) * DIM + kofs + c * 8;
            cp16(dst, src);
        }
    };

    load_stage(0, 0);
    asm volatile("cp.async.commit_group;");
    load_stage(1, 1);
    asm volatile("cp.async.commit_group;");

    float acc[2][8][4];
    #pragma unroll
    for (int mf = 0; mf < 2; mf++)
        #pragma unroll
        for (int nf = 0; nf < 8; nf++)
            #pragma unroll
            for (int e = 0; e < 4; e++) acc[mf][nf][e] = 0.f;

    const int rl = lane & 15;
    const int cb16 = (lane >> 4) << 4;

    for (int ck = 0; ck < NCHUNK; ck++) {
        asm volatile("cp.async.wait_group 1;");
        __syncthreads();
        if (ck + 2 < NCHUNK) load_stage(ck + 2, (ck + 2) % GSTAGES);
        asm volatile("cp.async.commit_group;");

        const uint32_t sb = sbase + (ck % GSTAGES) * STAGE_B;
        #pragma unroll
        for (int k16 = 0; k16 < 2; k16++) {
            const int cb = k16 * 32 + cb16;
            uint32_t ah[2][4], al[2][4], bh[8][2], bl[8][2];
            #pragma unroll
            for (int mf = 0; mf < 2; mf++) {
                const uint32_t ra = (wm * 32 + mf * 16 + rl) * RS + cb;
                ldm4(ah[mf], sb + ra);
                ldm4(al[mf], sb + TILE_B + ra);
            }
            #pragma unroll
            for (int p = 0; p < 4; p++) {
                const uint32_t rb = (wn * 64 + p * 16 + rl) * RS + cb;
                uint32_t t[4];
                ldm4(t, sb + 2 * TILE_B + rb);
                bh[2 * p][0] = t[0]; bh[2 * p][1] = t[2];
                bh[2 * p + 1][0] = t[1]; bh[2 * p + 1][1] = t[3];
                ldm4(t, sb + 3 * TILE_B + rb);
                bl[2 * p][0] = t[0]; bl[2 * p][1] = t[2];
                bl[2 * p + 1][0] = t[1]; bl[2 * p + 1][1] = t[3];
            }
            // term-batched: 16 independent MMAs per term
            #pragma unroll
            for (int mf = 0; mf < 2; mf++)
                #pragma unroll
                for (int nf = 0; nf < 8; nf++)
                    mma_bf16(acc[mf][nf], ah[mf], bh[nf]);
            #pragma unroll
            for (int mf = 0; mf < 2; mf++)
                #pragma unroll
                for (int nf = 0; nf < 8; nf++)
                    mma_bf16(acc[mf][nf], al[mf], bh[nf]);
            #pragma unroll
            for (int mf = 0; mf < 2; mf++)
                #pragma unroll
                for (int nf = 0; nf < 8; nf++)
                    mma_bf16(acc[mf][nf], ah[mf], bl[nf]);
        }
    }

    const int gid = lane >> 2;
    const int cq = (lane & 3) * 2;
    #pragma unroll
    for (int mf = 0; mf < 2; mf++) {
        const int row0 = m0 + wm * 32 + mf * 16 + gid;
        #pragma unroll
        for (int nf = 0; nf < 8; nf++) {
            const int col = n0 + wn * 64 + nf * 8 + cq;
            const float2 bv = *(const float2*)(bias + col);
            float2 v0, v1;
            v0.x = acc[mf][nf][0] + bv.x;
            v0.y = acc[mf][nf][1] + bv.y;
            v1.x = acc[mf][nf][2] + bv.x;
            v1.y = acc[mf][nf][3] + bv.y;
            if (act) {
                v0.x = (v0.x > 0.f) ? v0.x + 1.f : __expf(v0.x);
                v0.y = (v0.y > 0.f) ? v0.y + 1.f : __expf(v0.y);
                v1.x = (v1.x > 0.f) ? v1.x + 1.f : __expf(v1.x);
                v1.y = (v1.y > 0.f) ? v1.y + 1.f : __expf(v1.y);
            }
            *(float2*)(C + (size_t)row0 * DIM + col) = v0;
            *(float2*)(C + (size_t)(row0 + 8) * DIM + col) = v1;
        }
    }
}

// ---------------------------------------------------------------------------
// fused Q/K/V GEMM: grid.x in [0,24): matrix = x>>3, n-tile = x&7
// ---------------------------------------------------------------------------
__global__ __launch_bounds__(256, 1)
void gemm_qkv_kernel(const __nv_bfloat16* __restrict__ xh,
                     const __nv_bfloat16* __restrict__ xl,
                     const __nv_bfloat16* __restrict__ wqh,
                     const __nv_bfloat16* __restrict__ wql,
                     const __nv_bfloat16* __restrict__ wkh,
                     const __nv_bfloat16* __restrict__ wkl,
                     const __nv_bfloat16* __restrict__ wvh,
                     const __nv_bfloat16* __restrict__ wvl,
                     const float* __restrict__ bq,
                     const float* __restrict__ bk,
                     const float* __restrict__ bv)
{
    extern __shared__ __align__(16) char smem[];
    const int nb = blockIdx.x;
    const int mat = nb >> 3;
    const int n0 = (nb & 7) * GBN;
    const int m0 = blockIdx.y * GBM;

    const __nv_bfloat16 *Bh, *Bl;
    const float* bias;
    float* C;
    int act;
    if (mat == 0)      { Bh = wqh; Bl = wql; bias = bq; C = g_Q; act = 1; }
    else if (mat == 1) { Bh = wkh; Bl = wkl; bias = bk; C = g_K; act = 1; }
    else               { Bh = wvh; Bl = wvl; bias = bv; C = g_V; act = 0; }

    gemm_body(xh, xl, Bh, Bl, bias, C, m0, n0, act, smem);
}

// ---------------------------------------------------------------------------
// single GEMM (output projection)
// ---------------------------------------------------------------------------
__global__ __launch_bounds__(256, 1)
void gemm_o_kernel(const __nv_bfloat16* __restrict__ Ah,
                   const __nv_bfloat16* __restrict__ Al,
                   const __nv_bfloat16* __restrict__ Bh,
                   const __nv_bfloat16* __restrict__ Bl,
                   const float* __restrict__ bias,
                   float* __restrict__ C)
{
    extern __shared__ __align__(16) char smem[];
    gemm_body(Ah, Al, Bh, Bl, bias, C,
              blockIdx.y * GBM, blockIdx.x * GBN, 0, smem);
}

// ---------------------------------------------------------------------------
__global__ void zero_kv_kernel()
{
    const int i = blockIdx.x * 256 + threadIdx.x;
    if (i < BDIM * HEADS * HD * HD) g_KV[i] = 0.f;
    if (i < BDIM * HEADS * HD)      g_Ksum[i] = 0.f;
}

// ---------------------------------------------------------------------------
// KV[b,h,d,v] = sum_n K[b,n,h,d] * V[b,n,h,v];  Ksum[b,h,d] = sum_n K
// ---------------------------------------------------------------------------
__global__ __launch_bounds__(256)
void kv_kernel(const float* __restrict__ K, const float* __restrict__ V)
{
    const int bh = blockIdx.x;
    const int seg = blockIdx.y;
    const int b = bh >> 4, h = bh & 15;
    const int tid = threadIdx.x;

    __shared__ __align__(16) float ks[8][64];
    __shared__ __align__(16) float vs[8][64];

    const int dq = tid >> 4;
    const int vq = tid & 15;
    float acc[4][4];
    #pragma unroll
    for (int a = 0; a < 4; a++)
        #pragma unroll
        for (int c = 0; c < 4; c++) acc[a][c] = 0.f;
    float ksacc = 0.f;

    const size_t base = ((size_t)b * NSEQ) * DIM + h * HD;
    const int row8 = tid >> 5;
    const int q = tid & 31;
    const bool isV = (q >= 16);
    const int c4 = (q & 15) * 4;

    const int nbeg = seg * (NSEQ / 8);
    const int nend = nbeg + (NSEQ / 8);

    for (int n0 = nbeg; n0 < nend; n0 += 8) {
        const size_t g = base + (size_t)(n0 + row8) * DIM + c4;
        float4 val = isV ? *(const float4*)(V + g) : *(const float4*)(K + g);
        float* dst = isV ? &vs[row8][c4] : &ks[row8][c4];
        *(float4*)dst = val;
        __syncthreads();
        #pragma unroll
        for (int i = 0; i < 8; i++) {
            const float4 kv = *(const float4*)&ks[i][dq * 4];
            const float4 vv = *(const float4*)&vs[i][vq * 4];
            acc[0][0] += kv.x * vv.x; acc[0][1] += kv.x * vv.y;
            acc[0][2] += kv.x * vv.z; acc[0][3] += kv.x * vv.w;
            acc[1][0] += kv.y * vv.x; acc[1][1] += kv.y * vv.y;
            acc[1][2] += kv.y * vv.z; acc[1][3] += kv.y * vv.w;
            acc[2][0] += kv.z * vv.x; acc[2][1] += kv.z * vv.y;
            acc[2][2] += kv.z * vv.z; acc[2][3] += kv.z * vv.w;
            acc[3][0] += kv.w * vv.x; acc[3][1] += kv.w * vv.y;
            acc[3][2] += kv.w * vv.z; acc[3][3] += kv.w * vv.w;
        }
        if (tid < 64) {
            #pragma unroll
            for (int i = 0; i < 8; i++) ksacc += ks[i][tid];
        }
        __syncthreads();
    }

    float* kvout = g_KV + bh * (HD * HD);
    #pragma unroll
    for (int a = 0; a < 4; a++)
        #pragma unroll
        for (int c = 0; c < 4; c++)
            atomicAdd(&kvout[(dq * 4 + a) * HD + vq * 4 + c], acc[a][c]);
    if (tid < 64) atomicAdd(&g_Ksum[bh * HD + tid], ksacc);
}

// ---------------------------------------------------------------------------
// attn -> bf16 hi/lo splits directly (consumed by gemm_o)
// ---------------------------------------------------------------------------
__global__ __launch_bounds__(256)
void attn_kernel(const float* __restrict__ Q,
                 const float* __restrict__ stdp,
                 __nv_bfloat16* __restrict__ outh,
                 __nv_bfloat16* __restrict__ outl)
{
    const int bh = blockIdx.y;
    const int b = bh >> 4, h = bh & 15;
    const int n0 = blockIdx.x * 64;
    const int tid = threadIdx.x;

    __shared__ __align__(16) float qs[64][68];
    __shared__ __align__(16) float kvs[64][68];
    __shared__ float ksum_s[64];

    const size_t qbase = ((size_t)b * NSEQ + n0) * DIM + h * HD;
    #pragma unroll
    for (int i = 0; i < 4; i++) {
        const int slot = tid + i * 256;
        const int r = slot >> 4;
        const int c4 = (slot & 15) * 4;
        *(float4*)&qs[r][c4]  = *(const float4*)(Q + qbase + (size_t)r * DIM + c4);
        *(float4*)&kvs[r][c4] = *(const float4*)(g_KV + bh * (HD * HD) + r * HD + c4);
    }
    if (tid < 64) ksum_s[tid] = g_Ksum[bh * HD + tid];
    __syncthreads();

    const int r = tid >> 2;
    const int quad = tid & 3;
    float acc[16];
    #pragma unroll
    for (int j = 0; j < 16; j++) acc[j] = 0.f;
    float den = 0.f;

    #pragma unroll 4
    for (int d = 0; d < 64; d++) {
        const float qv = qs[r][d];
        den += qv * ksum_s[d];
        const float4 k0 = *(const float4*)&kvs[d][quad * 16 + 0];
        const float4 k1 = *(const float4*)&kvs[d][quad * 16 + 4];
        const float4 k2 = *(const float4*)&kvs[d][quad * 16 + 8];
        const float4 k3 = *(const float4*)&kvs[d][quad * 16 + 12];
        acc[0]  += qv * k0.x; acc[1]  += qv * k0.y; acc[2]  += qv * k0.z; acc[3]  += qv * k0.w;
        acc[4]  += qv * k1.x; acc[5]  += qv * k1.y; acc[6]  += qv * k1.z; acc[7]  += qv * k1.w;
        acc[8]  += qv * k2.x; acc[9]  += qv * k2.y; acc[10] += qv * k2.z; acc[11] += qv * k2.w;
        acc[12] += qv * k3.x; acc[13] += qv * k3.y; acc[14] += qv * k3.z; acc[15] += qv * k3.w;
    }

    const float sig = 1.f / (1.f + expf(-stdp[h]));
    const float scale = sig / (den + 1e-6f);

    const size_t obase = ((size_t)b * NSEQ + n0 + r) * DIM + h * HD + quad * 16;
    #pragma unroll
    for (int j = 0; j < 4; j++) {
        __nv_bfloat162 hh[2], ll[2];
        #pragma unroll
        for (int e = 0; e < 2; e++) {
            float v0 = acc[j * 4 + 2 * e]     * scale;
            float v1 = acc[j * 4 + 2 * e + 1] * scale;
            __nv_bfloat16 h0 = __float2bfloat16_rn(v0);
            __nv_bfloat16 h1 = __float2bfloat16_rn(v1);
            __nv_bfloat16 l0 = __float2bfloat16_rn(v0 - __bfloat162float(h0));
            __nv_bfloat16 l1 = __float2bfloat16_rn(v1 - __bfloat162float(h1));
            hh[e] = __halves2bfloat162(h0, h1);
            ll[e] = __halves2bfloat162(l0, l1);
        }
        *(__nv_bfloat162*)(outh + obase + j * 4)     = hh[0];
        *(__nv_bfloat162*)(outh + obase + j * 4 + 2) = hh[1];
        *(__nv_bfloat162*)(outl + obase + j * 4)     = ll[0];
        *(__nv_bfloat162*)(outl + obase + j * 4 + 2) = ll[1];
    }
}

// ---------------------------------------------------------------------------
__global__ void tail_kernel(const float* __restrict__ stdp,
                            float* __restrict__ out, int extra)
{
    const int i = threadIdx.x + blockIdx.x * blockDim.x;
    if (i < extra) {
        out[(size_t)MTOT * DIM + i] = (i < HEADS) ? stdp[i] : 0.f;
    }
}

// ---------------------------------------------------------------------------
extern "C" void kernel_launch(void* const* d_in, const int* in_sizes, int n_in,
                              void* d_out, int out_size)
{
    const float* x    = (const float*)d_in[0];
    const float* Wq   = (const float*)d_in[1];
    const float* bq   = (const float*)d_in[2];
    const float* Wk   = (const float*)d_in[3];
    const float* bk   = (const float*)d_in[4];
    const float* Wv   = (const float*)d_in[5];
    const float* bv   = (const float*)d_in[6];
    const float* Wo   = (const float*)d_in[7];
    const float* bo   = (const float*)d_in[8];
    const float* stdp = (const float*)d_in[9];
    float* out = (float*)d_out;

    float *pQ, *pK, *pV;
    cudaGetSymbolAddress((void**)&pQ, g_Q);
    cudaGetSymbolAddress((void**)&pK, g_K);
    cudaGetSymbolAddress((void**)&pV, g_V);

    __nv_bfloat16 *xh, *xl, *ah, *al, *wqh, *wql, *wkh, *wkl, *wvh, *wvl, *woh, *wol;
    cudaGetSymbolAddress((void**)&xh, g_xh);
    cudaGetSymbolAddress((void**)&xl, g_xl);
    cudaGetSymbolAddress((void**)&ah, g_ah);
    cudaGetSymbolAddress((void**)&al, g_al);
    cudaGetSymbolAddress((void**)&wqh, g_wqh);
    cudaGetSymbolAddress((void**)&wql, g_wql);
    cudaGetSymbolAddress((void**)&wkh, g_wkh);
    cudaGetSymbolAddress((void**)&wkl, g_wkl);
    cudaGetSymbolAddress((void**)&wvh, g_wvh);
    cudaGetSymbolAddress((void**)&wvl, g_wvl);
    cudaGetSymbolAddress((void**)&woh, g_woh);
    cudaGetSymbolAddress((void**)&wol, g_wol);

    cudaFuncSetAttribute(gemm_qkv_kernel,
                         cudaFuncAttributeMaxDynamicSharedMemorySize, SMEMG);
    cudaFuncSetAttribute(gemm_o_kernel,
                         cudaFuncAttributeMaxDynamicSharedMemorySize, SMEMG);

    const int nx4 = MTOT * DIM / 4;
    const int nw4 = DIM * DIM / 4;

    // launches 0-3: weight splits; 4: x split; 5: fused QKV GEMM (profiled)
    split_kernel<<<nw4 / 256, 256>>>(Wq, wqh, wql, nw4);
    split_kernel<<<nw4 / 256, 256>>>(Wk, wkh, wkl, nw4);
    split_kernel<<<nw4 / 256, 256>>>(Wv, wvh, wvl, nw4);
    split_kernel<<<nw4 / 256, 256>>>(Wo, woh, wol, nw4);
    split_kernel<<<nx4 / 256, 256>>>(x, xh, xl, nx4);

    gemm_qkv_kernel<<<dim3(24, MTOT / GBM), 256, SMEMG>>>(
        xh, xl, wqh, wql, wkh, wkl, wvh, wvl, bq, bk, bv);

    zero_kv_kernel<<<(BDIM * HEADS * HD * HD + 255) / 256, 256>>>();
    kv_kernel<<<dim3(BDIM * HEADS, 8), 256>>>(pK, pV);
    attn_kernel<<<dim3(NSEQ / 64, BDIM * HEADS), 256>>>(pQ, stdp, ah, al);

    gemm_o_kernel<<<dim3(DIM / GBN, MTOT / GBM), 256, SMEMG>>>(
        ah, al, woh, wol, bo, out);

    const int extra = out_size - MTOT * DIM;
    if (extra > 0) {
        tail_kernel<<<(extra + 255) / 256, 256>>>(stdp, out, extra);
    }
}

// round 6
// speedup vs baseline: 2.0883x; 1.0600x over previous
#include <cuda_runtime.h>
#include <cuda_bf16.h>
#include <math.h>
#include <stdint.h>

// ---------------------------------------------------------------------------
// SpikeAttention (linear attention, ELU+1 feature map)
//   B=4, N=4096, DIM=1024, HEADS=16, HEAD_DIM=64
// Round 6: GBK=64 / 3-stage pipeline (halved sync count), fused weight split.
// 3-term bf16 mma.sync split GEMMs (A*B ~= Ah*Bh + Al*Bh + Ah*Bl).
// ---------------------------------------------------------------------------

#define BDIM  4
#define NSEQ  4096
#define DIM   1024
#define HEADS 16
#define HD    64
#define MTOT  (BDIM * NSEQ)          // 16384

__device__ float g_Q[(size_t)MTOT * DIM];
__device__ float g_K[(size_t)MTOT * DIM];
__device__ float g_V[(size_t)MTOT * DIM];
__device__ float g_KV[BDIM * HEADS * HD * HD];
__device__ float g_Ksum[BDIM * HEADS * HD];

__device__ __align__(16) __nv_bfloat16 g_xh[(size_t)MTOT * DIM];
__device__ __align__(16) __nv_bfloat16 g_xl[(size_t)MTOT * DIM];
__device__ __align__(16) __nv_bfloat16 g_ah[(size_t)MTOT * DIM];
__device__ __align__(16) __nv_bfloat16 g_al[(size_t)MTOT * DIM];
__device__ __align__(16) __nv_bfloat16 g_wh[4][DIM * DIM];   // q,k,v,o hi
__device__ __align__(16) __nv_bfloat16 g_wl[4][DIM * DIM];   // q,k,v,o lo

// ---------------------------------------------------------------------------
__device__ __forceinline__ void split4(const float* __restrict__ src,
                                       __nv_bfloat16* __restrict__ hi,
                                       __nv_bfloat16* __restrict__ lo, int i)
{
    float4 f = ((const float4*)src)[i];
    __nv_bfloat16 h0 = __float2bfloat16_rn(f.x);
    __nv_bfloat16 h1 = __float2bfloat16_rn(f.y);
    __nv_bfloat16 h2 = __float2bfloat16_rn(f.z);
    __nv_bfloat16 h3 = __float2bfloat16_rn(f.w);
    __nv_bfloat16 l0 = __float2bfloat16_rn(f.x - __bfloat162float(h0));
    __nv_bfloat16 l1 = __float2bfloat16_rn(f.y - __bfloat162float(h1));
    __nv_bfloat16 l2 = __float2bfloat16_rn(f.z - __bfloat162float(h2));
    __nv_bfloat16 l3 = __float2bfloat16_rn(f.w - __bfloat162float(h3));
    ((__nv_bfloat162*)hi)[2 * i + 0] = __halves2bfloat162(h0, h1);
    ((__nv_bfloat162*)hi)[2 * i + 1] = __halves2bfloat162(h2, h3);
    ((__nv_bfloat162*)lo)[2 * i + 0] = __halves2bfloat162(l0, l1);
    ((__nv_bfloat162*)lo)[2 * i + 1] = __halves2bfloat162(l2, l3);
}

// all four weight matrices in one launch: grid.x = 4096, matrix = bid>>10
__global__ __launch_bounds__(256)
void wsplit_kernel(const float* __restrict__ Wq, const float* __restrict__ Wk,
                   const float* __restrict__ Wv, const float* __restrict__ Wo)
{
    const int mat = blockIdx.x >> 10;
    const int i = (blockIdx.x & 1023) * 256 + threadIdx.x;
    const float* src = (mat == 0) ? Wq : (mat == 1) ? Wk : (mat == 2) ? Wv : Wo;
    split4(src, g_wh[mat], g_wl[mat], i);
}

__global__ __launch_bounds__(256)
void xsplit_kernel(const float* __restrict__ x)
{
    const int i = blockIdx.x * 256 + threadIdx.x;
    split4(x, g_xh, g_xl, i);
}

// ===========================================================================
// GEMM core: 128x128 tile, GBK=64, 3-stage cp.async, 256 threads, 8 warps.
// ===========================================================================
#define GBM 128
#define GBN 128
#define GBK 64
#define NCHUNK (DIM / GBK)           // 16
#define RS 144                        // 128B data + 16B pad
#define TILE_B (128 * RS)             // 18432
#define STAGE_B (4 * TILE_B)          // 73728
#define GSTAGES 3
#define SMEMG (GSTAGES * STAGE_B)     // 221184

__device__ __forceinline__ uint32_t smem_u32(const void* p) {
    uint32_t a;
    asm("{ .reg .u64 t; cvta.to.shared.u64 t, %1; cvt.u32.u64 %0, t; }"
        : "=r"(a) : "l"(p));
    return a;
}
__device__ __forceinline__ void cp16(uint32_t dst, const void* src) {
    asm volatile("cp.async.cg.shared.global [%0], [%1], 16;"
                 :: "r"(dst), "l"(src));
}
__device__ __forceinline__ void ldm4(uint32_t* r, uint32_t addr) {
    asm volatile("ldmatrix.sync.aligned.m8n8.x4.shared.b16 {%0,%1,%2,%3}, [%4];"
                 : "=r"(r[0]), "=r"(r[1]), "=r"(r[2]), "=r"(r[3]) : "r"(addr));
}
__device__ __forceinline__ void mma_bf16(float* c, const uint32_t* a,
                                         const uint32_t* b) {
    asm volatile(
        "mma.sync.aligned.m16n8k16.row.col.f32.bf16.bf16.f32 "
        "{%0,%1,%2,%3}, {%4,%5,%6,%7}, {%8,%9}, {%0,%1,%2,%3};"
        : "+f"(c[0]), "+f"(c[1]), "+f"(c[2]), "+f"(c[3])
        : "r"(a[0]), "r"(a[1]), "r"(a[2]), "r"(a[3]), "r"(b[0]), "r"(b[1]));
}

__device__ __forceinline__
void gemm_body(const __nv_bfloat16* __restrict__ Ah,
               const __nv_bfloat16* __restrict__ Al,
               const __nv_bfloat16* __restrict__ Bh,
               const __nv_bfloat16* __restrict__ Bl,
               const float* __restrict__ bias,
               float* __restrict__ C,
               int m0, int n0, int act, char* smem)
{
    const uint32_t sbase = smem_u32(smem);
    const int tid = threadIdx.x;
    const int lane = tid & 31;
    const int wid = tid >> 5;
    const int wm = wid & 3;
    const int wn = wid >> 2;

    // stage loader: 4096 x 16B chunks, 16 per thread
    auto load_stage = [&](int ck, int slot) {
        const uint32_t sb = sbase + slot * STAGE_B;
        const int kofs = ck * GBK;
        #pragma unroll
        for (int i = 0; i < 16; i++) {
            const int id = tid + i * 256;        // 0..4095
            const int tile = id >> 10;           // 0:Ah 1:Al 2:Bh 3:Bl
            const int r = (id >> 3) & 127;
            const int c = id & 7;
            const uint32_t dst = sb + tile * TILE_B + r * RS + c * 16;
            const __nv_bfloat16* src;
            if (tile == 0)      src = Ah + (size_t)(m0 + r) * DIM + kofs + c * 8;
            else if (tile == 1) src = Al + (size_t)(m0 + r) * DIM + kofs + c * 8;
            else if (tile == 2) src = Bh + (size_t)(n0 + r) * DIM + kofs + c * 8;
            else                src = Bl + (size_t)(n0 + r) * DIM + kofs + c * 8;
            cp16(dst, src);
        }
    };

    load_stage(0, 0);
    asm volatile("cp.async.commit_group;");
    load_stage(1, 1);
    asm volatile("cp.async.commit_group;");

    float acc[2][8][4];
    #pragma unroll
    for (int mf = 0; mf < 2; mf++)
        #pragma unroll
        for (int nf = 0; nf < 8; nf++)
            #pragma unroll
            for (int e = 0; e < 4; e++) acc[mf][nf][e] = 0.f;

    const int rl = lane & 15;
    const int cb16 = (lane >> 4) << 4;

    for (int ck = 0; ck < NCHUNK; ck++) {
        asm volatile("cp.async.wait_group 1;");
        __syncthreads();
        if (ck + 2 < NCHUNK) load_stage(ck + 2, (ck + 2) % GSTAGES);
        asm volatile("cp.async.commit_group;");

        const uint32_t sb = sbase + (ck % GSTAGES) * STAGE_B;
        #pragma unroll
        for (int k16 = 0; k16 < 4; k16++) {
            const int cb = k16 * 32 + cb16;
            uint32_t ah[2][4], al[2][4], bh[8][2], bl[8][2];
            #pragma unroll
            for (int mf = 0; mf < 2; mf++) {
                const uint32_t ra = (wm * 32 + mf * 16 + rl) * RS + cb;
                ldm4(ah[mf], sb + ra);
                ldm4(al[mf], sb + TILE_B + ra);
            }
            #pragma unroll
            for (int p = 0; p < 4; p++) {
                const uint32_t rb = (wn * 64 + p * 16 + rl) * RS + cb;
                uint32_t t[4];
                ldm4(t, sb + 2 * TILE_B + rb);
                bh[2 * p][0] = t[0]; bh[2 * p][1] = t[2];
                bh[2 * p + 1][0] = t[1]; bh[2 * p + 1][1] = t[3];
                ldm4(t, sb + 3 * TILE_B + rb);
                bl[2 * p][0] = t[0]; bl[2 * p][1] = t[2];
                bl[2 * p + 1][0] = t[1]; bl[2 * p + 1][1] = t[3];
            }
            #pragma unroll
            for (int mf = 0; mf < 2; mf++)
                #pragma unroll
                for (int nf = 0; nf < 8; nf++)
                    mma_bf16(acc[mf][nf], ah[mf], bh[nf]);
            #pragma unroll
            for (int mf = 0; mf < 2; mf++)
                #pragma unroll
                for (int nf = 0; nf < 8; nf++)
                    mma_bf16(acc[mf][nf], al[mf], bh[nf]);
            #pragma unroll
            for (int mf = 0; mf < 2; mf++)
                #pragma unroll
                for (int nf = 0; nf < 8; nf++)
                    mma_bf16(acc[mf][nf], ah[mf], bl[nf]);
        }
    }

    const int gid = lane >> 2;
    const int cq = (lane & 3) * 2;
    #pragma unroll
    for (int mf = 0; mf < 2; mf++) {
        const int row0 = m0 + wm * 32 + mf * 16 + gid;
        #pragma unroll
        for (int nf = 0; nf < 8; nf++) {
            const int col = n0 + wn * 64 + nf * 8 + cq;
            const float2 bv = *(const float2*)(bias + col);
            float2 v0, v1;
            v0.x = acc[mf][nf][0] + bv.x;
            v0.y = acc[mf][nf][1] + bv.y;
            v1.x = acc[mf][nf][2] + bv.x;
            v1.y = acc[mf][nf][3] + bv.y;
            if (act) {
                v0.x = (v0.x > 0.f) ? v0.x + 1.f : __expf(v0.x);
                v0.y = (v0.y > 0.f) ? v0.y + 1.f : __expf(v0.y);
                v1.x = (v1.x > 0.f) ? v1.x + 1.f : __expf(v1.x);
                v1.y = (v1.y > 0.f) ? v1.y + 1.f : __expf(v1.y);
            }
            *(float2*)(C + (size_t)row0 * DIM + col) = v0;
            *(float2*)(C + (size_t)(row0 + 8) * DIM + col) = v1;
        }
    }
}

// ---------------------------------------------------------------------------
__global__ __launch_bounds__(256, 1)
void gemm_qkv_kernel(const float* __restrict__ bq,
                     const float* __restrict__ bk,
                     const float* __restrict__ bv)
{
    extern __shared__ __align__(16) char smem[];
    const int nb = blockIdx.x;
    const int mat = nb >> 3;
    const int n0 = (nb & 7) * GBN;
    const int m0 = blockIdx.y * GBM;

    const float* bias;
    float* C;
    int act;
    if (mat == 0)      { bias = bq; C = g_Q; act = 1; }
    else if (mat == 1) { bias = bk; C = g_K; act = 1; }
    else               { bias = bv; C = g_V; act = 0; }

    gemm_body(g_xh, g_xl, g_wh[mat], g_wl[mat], bias, C, m0, n0, act, smem);
}

__global__ __launch_bounds__(256, 1)
void gemm_o_kernel(const float* __restrict__ bias, float* __restrict__ C)
{
    extern __shared__ __align__(16) char smem[];
    gemm_body(g_ah, g_al, g_wh[3], g_wl[3], bias, C,
              blockIdx.y * GBM, blockIdx.x * GBN, 0, smem);
}

// ---------------------------------------------------------------------------
__global__ void zero_kv_kernel()
{
    const int i = blockIdx.x * 256 + threadIdx.x;
    if (i < BDIM * HEADS * HD * HD) g_KV[i] = 0.f;
    if (i < BDIM * HEADS * HD)      g_Ksum[i] = 0.f;
}

// ---------------------------------------------------------------------------
__global__ __launch_bounds__(256)
void kv_kernel(const float* __restrict__ K, const float* __restrict__ V)
{
    const int bh = blockIdx.x;
    const int seg = blockIdx.y;
    const int b = bh >> 4, h = bh & 15;
    const int tid = threadIdx.x;

    __shared__ __align__(16) float ks[8][64];
    __shared__ __align__(16) float vs[8][64];

    const int dq = tid >> 4;
    const int vq = tid & 15;
    float acc[4][4];
    #pragma unroll
    for (int a = 0; a < 4; a++)
        #pragma unroll
        for (int c = 0; c < 4; c++) acc[a][c] = 0.f;
    float ksacc = 0.f;

    const size_t base = ((size_t)b * NSEQ) * DIM + h * HD;
    const int row8 = tid >> 5;
    const int q = tid & 31;
    const bool isV = (q >= 16);
    const int c4 = (q & 15) * 4;

    const int nbeg = seg * (NSEQ / 8);
    const int nend = nbeg + (NSEQ / 8);

    for (int n0 = nbeg; n0 < nend; n0 += 8) {
        const size_t g = base + (size_t)(n0 + row8) * DIM + c4;
        float4 val = isV ? *(const float4*)(V + g) : *(const float4*)(K + g);
        float* dst = isV ? &vs[row8][c4] : &ks[row8][c4];
        *(float4*)dst = val;
        __syncthreads();
        #pragma unroll
        for (int i = 0; i < 8; i++) {
            const float4 kv = *(const float4*)&ks[i][dq * 4];
            const float4 vv = *(const float4*)&vs[i][vq * 4];
            acc[0][0] += kv.x * vv.x; acc[0][1] += kv.x * vv.y;
            acc[0][2] += kv.x * vv.z; acc[0][3] += kv.x * vv.w;
            acc[1][0] += kv.y * vv.x; acc[1][1] += kv.y * vv.y;
            acc[1][2] += kv.y * vv.z; acc[1][3] += kv.y * vv.w;
            acc[2][0] += kv.z * vv.x; acc[2][1] += kv.z * vv.y;
            acc[2][2] += kv.z * vv.z; acc[2][3] += kv.z * vv.w;
            acc[3][0] += kv.w * vv.x; acc[3][1] += kv.w * vv.y;
            acc[3][2] += kv.w * vv.z; acc[3][3] += kv.w * vv.w;
        }
        if (tid < 64) {
            #pragma unroll
            for (int i = 0; i < 8; i++) ksacc += ks[i][tid];
        }
        __syncthreads();
    }

    float* kvout = g_KV + bh * (HD * HD);
    #pragma unroll
    for (int a = 0; a < 4; a++)
        #pragma unroll
        for (int c = 0; c < 4; c++)
            atomicAdd(&kvout[(dq * 4 + a) * HD + vq * 4 + c], acc[a][c]);
    if (tid < 64) atomicAdd(&g_Ksum[bh * HD + tid], ksacc);
}

// ---------------------------------------------------------------------------
__global__ __launch_bounds__(256)
void attn_kernel(const float* __restrict__ Q,
                 const float* __restrict__ stdp,
                 __nv_bfloat16* __restrict__ outh,
                 __nv_bfloat16* __restrict__ outl)
{
    const int bh = blockIdx.y;
    const int b = bh >> 4, h = bh & 15;
    const int n0 = blockIdx.x * 64;
    const int tid = threadIdx.x;

    __shared__ __align__(16) float qs[64][68];
    __shared__ __align__(16) float kvs[64][68];
    __shared__ float ksum_s[64];

    const size_t qbase = ((size_t)b * NSEQ + n0) * DIM + h * HD;
    #pragma unroll
    for (int i = 0; i < 4; i++) {
        const int slot = tid + i * 256;
        const int r = slot >> 4;
        const int c4 = (slot & 15) * 4;
        *(float4*)&qs[r][c4]  = *(const float4*)(Q + qbase + (size_t)r * DIM + c4);
        *(float4*)&kvs[r][c4] = *(const float4*)(g_KV + bh * (HD * HD) + r * HD + c4);
    }
    if (tid < 64) ksum_s[tid] = g_Ksum[bh * HD + tid];
    __syncthreads();

    const int r = tid >> 2;
    const int quad = tid & 3;
    float acc[16];
    #pragma unroll
    for (int j = 0; j < 16; j++) acc[j] = 0.f;
    float den = 0.f;

    #pragma unroll 4
    for (int d = 0; d < 64; d++) {
        const float qv = qs[r][d];
        den += qv * ksum_s[d];
        const float4 k0 = *(const float4*)&kvs[d][quad * 16 + 0];
        const float4 k1 = *(const float4*)&kvs[d][quad * 16 + 4];
        const float4 k2 = *(const float4*)&kvs[d][quad * 16 + 8];
        const float4 k3 = *(const float4*)&kvs[d][quad * 16 + 12];
        acc[0]  += qv * k0.x; acc[1]  += qv * k0.y; acc[2]  += qv * k0.z; acc[3]  += qv * k0.w;
        acc[4]  += qv * k1.x; acc[5]  += qv * k1.y; acc[6]  += qv * k1.z; acc[7]  += qv * k1.w;
        acc[8]  += qv * k2.x; acc[9]  += qv * k2.y; acc[10] += qv * k2.z; acc[11] += qv * k2.w;
        acc[12] += qv * k3.x; acc[13] += qv * k3.y; acc[14] += qv * k3.z; acc[15] += qv * k3.w;
    }

    const float sig = 1.f / (1.f + expf(-stdp[h]));
    const float scale = sig / (den + 1e-6f);

    const size_t obase = ((size_t)b * NSEQ + n0 + r) * DIM + h * HD + quad * 16;
    #pragma unroll
    for (int j = 0; j < 4; j++) {
        __nv_bfloat162 hh[2], ll[2];
        #pragma unroll
        for (int e = 0; e < 2; e++) {
            float v0 = acc[j * 4 + 2 * e]     * scale;
            float v1 = acc[j * 4 + 2 * e + 1] * scale;
            __nv_bfloat16 h0 = __float2bfloat16_rn(v0);
            __nv_bfloat16 h1 = __float2bfloat16_rn(v1);
            __nv_bfloat16 l0 = __float2bfloat16_rn(v0 - __bfloat162float(h0));
            __nv_bfloat16 l1 = __float2bfloat16_rn(v1 - __bfloat162float(h1));
            hh[e] = __halves2bfloat162(h0, h1);
            ll[e] = __halves2bfloat162(l0, l1);
        }
        *(__nv_bfloat162*)(outh + obase + j * 4)     = hh[0];
        *(__nv_bfloat162*)(outh + obase + j * 4 + 2) = hh[1];
        *(__nv_bfloat162*)(outl + obase + j * 4)     = ll[0];
        *(__nv_bfloat162*)(outl + obase + j * 4 + 2) = ll[1];
    }
}

// ---------------------------------------------------------------------------
__global__ void tail_kernel(const float* __restrict__ stdp,
                            float* __restrict__ out, int extra)
{
    const int i = threadIdx.x + blockIdx.x * blockDim.x;
    if (i < extra) {
        out[(size_t)MTOT * DIM + i] = (i < HEADS) ? stdp[i] : 0.f;
    }
}

// ---------------------------------------------------------------------------
extern "C" void kernel_launch(void* const* d_in, const int* in_sizes, int n_in,
                              void* d_out, int out_size)
{
    const float* x    = (const float*)d_in[0];
    const float* Wq   = (const float*)d_in[1];
    const float* bq   = (const float*)d_in[2];
    const float* Wk   = (const float*)d_in[3];
    const float* bk   = (const float*)d_in[4];
    const float* Wv   = (const float*)d_in[5];
    const float* bv   = (const float*)d_in[6];
    const float* Wo   = (const float*)d_in[7];
    const float* bo   = (const float*)d_in[8];
    const float* stdp = (const float*)d_in[9];
    float* out = (float*)d_out;

    float *pQ, *pK, *pV;
    cudaGetSymbolAddress((void**)&pQ, g_Q);
    cudaGetSymbolAddress((void**)&pK, g_K);
    cudaGetSymbolAddress((void**)&pV, g_V);
    __nv_bfloat16 *ah, *al;
    cudaGetSymbolAddress((void**)&ah, g_ah);
    cudaGetSymbolAddress((void**)&al, g_al);

    cudaFuncSetAttribute(gemm_qkv_kernel,
                         cudaFuncAttributeMaxDynamicSharedMemorySize, SMEMG);
    cudaFuncSetAttribute(gemm_o_kernel,
                         cudaFuncAttributeMaxDynamicSharedMemorySize, SMEMG);

    const int nx4 = MTOT * DIM / 4;

    wsplit_kernel<<<4096, 256>>>(Wq, Wk, Wv, Wo);
    xsplit_kernel<<<nx4 / 256, 256>>>(x);

    gemm_qkv_kernel<<<dim3(24, MTOT / GBM), 256, SMEMG>>>(bq, bk, bv);

    zero_kv_kernel<<<(BDIM * HEADS * HD * HD + 255) / 256, 256>>>();
    kv_kernel<<<dim3(BDIM * HEADS, 8), 256>>>(pK, pV);
    attn_kernel<<<dim3(NSEQ / 64, BDIM * HEADS), 256>>>(pQ, stdp, ah, al);

    gemm_o_kernel<<<dim3(DIM / GBN, MTOT / GBM), 256, SMEMG>>>(bo, out);

    const int extra = out_size - MTOT * DIM;
    if (extra > 0) {
        tail_kernel<<<(extra + 255) / 256, 256>>>(stdp, out, extra);
    }
}

// round 7
// speedup vs baseline: 2.1144x; 1.0125x over previous
#include <cuda_runtime.h>
#include <cuda_bf16.h>
#include <math.h>
#include <stdint.h>

// ---------------------------------------------------------------------------
// SpikeAttention (linear attention, ELU+1 feature map)
//   B=4, N=4096, DIM=1024, HEADS=16, HEAD_DIM=64
// Round 7: launch reorder (gemm_qkv at profiled index 3), f32x2 packed FMAs
// in kv/attn middle kernels. 3-term bf16 mma.sync split GEMMs unchanged.
// ---------------------------------------------------------------------------

#define BDIM  4
#define NSEQ  4096
#define DIM   1024
#define HEADS 16
#define HD    64
#define MTOT  (BDIM * NSEQ)          // 16384

__device__ float g_Q[(size_t)MTOT * DIM];
__device__ float g_K[(size_t)MTOT * DIM];
__device__ float g_V[(size_t)MTOT * DIM];
__device__ float g_KV[BDIM * HEADS * HD * HD];
__device__ float g_Ksum[BDIM * HEADS * HD];

__device__ __align__(16) __nv_bfloat16 g_xh[(size_t)MTOT * DIM];
__device__ __align__(16) __nv_bfloat16 g_xl[(size_t)MTOT * DIM];
__device__ __align__(16) __nv_bfloat16 g_ah[(size_t)MTOT * DIM];
__device__ __align__(16) __nv_bfloat16 g_al[(size_t)MTOT * DIM];
__device__ __align__(16) __nv_bfloat16 g_wh[4][DIM * DIM];   // q,k,v,o hi
__device__ __align__(16) __nv_bfloat16 g_wl[4][DIM * DIM];   // q,k,v,o lo

// ---- packed f32x2 helpers -------------------------------------------------
__device__ __forceinline__ unsigned long long pack2(float x) {
    unsigned long long r;
    unsigned u = __float_as_uint(x);
    asm("mov.b64 %0, {%1, %1};" : "=l"(r) : "r"(u));
    return r;
}
__device__ __forceinline__ void ffma2(unsigned long long& d,
                                      unsigned long long a,
                                      unsigned long long b) {
    asm("fma.rn.f32x2 %0, %1, %2, %0;" : "+l"(d) : "l"(a), "l"(b));
}
__device__ __forceinline__ float lo2(unsigned long long v) {
    return __uint_as_float((unsigned)(v & 0xffffffffull));
}
__device__ __forceinline__ float hi2(unsigned long long v) {
    return __uint_as_float((unsigned)(v >> 32));
}

// ---------------------------------------------------------------------------
__device__ __forceinline__ void split4(const float* __restrict__ src,
                                       __nv_bfloat16* __restrict__ hi,
                                       __nv_bfloat16* __restrict__ lo, int i)
{
    float4 f = ((const float4*)src)[i];
    __nv_bfloat16 h0 = __float2bfloat16_rn(f.x);
    __nv_bfloat16 h1 = __float2bfloat16_rn(f.y);
    __nv_bfloat16 h2 = __float2bfloat16_rn(f.z);
    __nv_bfloat16 h3 = __float2bfloat16_rn(f.w);
    __nv_bfloat16 l0 = __float2bfloat16_rn(f.x - __bfloat162float(h0));
    __nv_bfloat16 l1 = __float2bfloat16_rn(f.y - __bfloat162float(h1));
    __nv_bfloat16 l2 = __float2bfloat16_rn(f.z - __bfloat162float(h2));
    __nv_bfloat16 l3 = __float2bfloat16_rn(f.w - __bfloat162float(h3));
    ((__nv_bfloat162*)hi)[2 * i + 0] = __halves2bfloat162(h0, h1);
    ((__nv_bfloat162*)hi)[2 * i + 1] = __halves2bfloat162(h2, h3);
    ((__nv_bfloat162*)lo)[2 * i + 0] = __halves2bfloat162(l0, l1);
    ((__nv_bfloat162*)lo)[2 * i + 1] = __halves2bfloat162(l2, l3);
}

__global__ __launch_bounds__(256)
void wsplit_kernel(const float* __restrict__ Wq, const float* __restrict__ Wk,
                   const float* __restrict__ Wv, const float* __restrict__ Wo)
{
    const int mat = blockIdx.x >> 10;
    const int i = (blockIdx.x & 1023) * 256 + threadIdx.x;
    const float* src = (mat == 0) ? Wq : (mat == 1) ? Wk : (mat == 2) ? Wv : Wo;
    split4(src, g_wh[mat], g_wl[mat], i);
}

__global__ __launch_bounds__(256)
void xsplit_kernel(const float* __restrict__ x)
{
    const int i = blockIdx.x * 256 + threadIdx.x;
    split4(x, g_xh, g_xl, i);
}

// ===========================================================================
// GEMM core: 128x128 tile, GBK=64, 3-stage cp.async, 256 threads, 8 warps.
// ===========================================================================
#define GBM 128
#define GBN 128
#define GBK 64
#define NCHUNK (DIM / GBK)           // 16
#define RS 144
#define TILE_B (128 * RS)
#define STAGE_B (4 * TILE_B)
#define GSTAGES 3
#define SMEMG (GSTAGES * STAGE_B)    // 221184

__device__ __forceinline__ uint32_t smem_u32(const void* p) {
    uint32_t a;
    asm("{ .reg .u64 t; cvta.to.shared.u64 t, %1; cvt.u32.u64 %0, t; }"
        : "=r"(a) : "l"(p));
    return a;
}
__device__ __forceinline__ void cp16(uint32_t dst, const void* src) {
    asm volatile("cp.async.cg.shared.global [%0], [%1], 16;"
                 :: "r"(dst), "l"(src));
}
__device__ __forceinline__ void ldm4(uint32_t* r, uint32_t addr) {
    asm volatile("ldmatrix.sync.aligned.m8n8.x4.shared.b16 {%0,%1,%2,%3}, [%4];"
                 : "=r"(r[0]), "=r"(r[1]), "=r"(r[2]), "=r"(r[3]) : "r"(addr));
}
__device__ __forceinline__ void mma_bf16(float* c, const uint32_t* a,
                                         const uint32_t* b) {
    asm volatile(
        "mma.sync.aligned.m16n8k16.row.col.f32.bf16.bf16.f32 "
        "{%0,%1,%2,%3}, {%4,%5,%6,%7}, {%8,%9}, {%0,%1,%2,%3};"
        : "+f"(c[0]), "+f"(c[1]), "+f"(c[2]), "+f"(c[3])
        : "r"(a[0]), "r"(a[1]), "r"(a[2]), "r"(a[3]), "r"(b[0]), "r"(b[1]));
}

__device__ __forceinline__
void gemm_body(const __nv_bfloat16* __restrict__ Ah,
               const __nv_bfloat16* __restrict__ Al,
               const __nv_bfloat16* __restrict__ Bh,
               const __nv_bfloat16* __restrict__ Bl,
               const float* __restrict__ bias,
               float* __restrict__ C,
               int m0, int n0, int act, char* smem)
{
    const uint32_t sbase = smem_u32(smem);
    const int tid = threadIdx.x;
    const int lane = tid & 31;
    const int wid = tid >> 5;
    const int wm = wid & 3;
    const int wn = wid >> 2;

    auto load_stage = [&](int ck, int slot) {
        const uint32_t sb = sbase + slot * STAGE_B;
        const int kofs = ck * GBK;
        #pragma unroll
        for (int i = 0; i < 16; i++) {
            const int id = tid + i * 256;
            const int tile = id >> 10;
            const int r = (id >> 3) & 127;
            const int c = id & 7;
            const uint32_t dst = sb + tile * TILE_B + r * RS + c * 16;
            const __nv_bfloat16* src;
            if (tile == 0)      src = Ah + (size_t)(m0 + r) * DIM + kofs + c * 8;
            else if (tile == 1) src = Al + (size_t)(m0 + r) * DIM + kofs + c * 8;
            else if (tile == 2) src = Bh + (size_t)(n0 + r) * DIM + kofs + c * 8;
            else                src = Bl + (size_t)(n0 + r) * DIM + kofs + c * 8;
            cp16(dst, src);
        }
    };

    load_stage(0, 0);
    asm volatile("cp.async.commit_group;");
    load_stage(1, 1);
    asm volatile("cp.async.commit_group;");

    float acc[2][8][4];
    #pragma unroll
    for (int mf = 0; mf < 2; mf++)
        #pragma unroll
        for (int nf = 0; nf < 8; nf++)
            #pragma unroll
            for (int e = 0; e < 4; e++) acc[mf][nf][e] = 0.f;

    const int rl = lane & 15;
    const int cb16 = (lane >> 4) << 4;

    for (int ck = 0; ck < NCHUNK; ck++) {
        asm volatile("cp.async.wait_group 1;");
        __syncthreads();
        if (ck + 2 < NCHUNK) load_stage(ck + 2, (ck + 2) % GSTAGES);
        asm volatile("cp.async.commit_group;");

        const uint32_t sb = sbase + (ck % GSTAGES) * STAGE_B;
        #pragma unroll
        for (int k16 = 0; k16 < 4; k16++) {
            const int cb = k16 * 32 + cb16;
            uint32_t ah[2][4], al[2][4], bh[8][2], bl[8][2];
            #pragma unroll
            for (int mf = 0; mf < 2; mf++) {
                const uint32_t ra = (wm * 32 + mf * 16 + rl) * RS + cb;
                ldm4(ah[mf], sb + ra);
                ldm4(al[mf], sb + TILE_B + ra);
            }
            #pragma unroll
            for (int p = 0; p < 4; p++) {
                const uint32_t rb = (wn * 64 + p * 16 + rl) * RS + cb;
                uint32_t t[4];
                ldm4(t, sb + 2 * TILE_B + rb);
                bh[2 * p][0] = t[0]; bh[2 * p][1] = t[2];
                bh[2 * p + 1][0] = t[1]; bh[2 * p + 1][1] = t[3];
                ldm4(t, sb + 3 * TILE_B + rb);
                bl[2 * p][0] = t[0]; bl[2 * p][1] = t[2];
                bl[2 * p + 1][0] = t[1]; bl[2 * p + 1][1] = t[3];
            }
            #pragma unroll
            for (int mf = 0; mf < 2; mf++)
                #pragma unroll
                for (int nf = 0; nf < 8; nf++)
                    mma_bf16(acc[mf][nf], ah[mf], bh[nf]);
            #pragma unroll
            for (int mf = 0; mf < 2; mf++)
                #pragma unroll
                for (int nf = 0; nf < 8; nf++)
                    mma_bf16(acc[mf][nf], al[mf], bh[nf]);
            #pragma unroll
            for (int mf = 0; mf < 2; mf++)
                #pragma unroll
                for (int nf = 0; nf < 8; nf++)
                    mma_bf16(acc[mf][nf], ah[mf], bl[nf]);
        }
    }

    const int gid = lane >> 2;
    const int cq = (lane & 3) * 2;
    #pragma unroll
    for (int mf = 0; mf < 2; mf++) {
        const int row0 = m0 + wm * 32 + mf * 16 + gid;
        #pragma unroll
        for (int nf = 0; nf < 8; nf++) {
            const int col = n0 + wn * 64 + nf * 8 + cq;
            const float2 bv = *(const float2*)(bias + col);
            float2 v0, v1;
            v0.x = acc[mf][nf][0] + bv.x;
            v0.y = acc[mf][nf][1] + bv.y;
            v1.x = acc[mf][nf][2] + bv.x;
            v1.y = acc[mf][nf][3] + bv.y;
            if (act) {
                v0.x = (v0.x > 0.f) ? v0.x + 1.f : __expf(v0.x);
                v0.y = (v0.y > 0.f) ? v0.y + 1.f : __expf(v0.y);
                v1.x = (v1.x > 0.f) ? v1.x + 1.f : __expf(v1.x);
                v1.y = (v1.y > 0.f) ? v1.y + 1.f : __expf(v1.y);
            }
            *(float2*)(C + (size_t)row0 * DIM + col) = v0;
            *(float2*)(C + (size_t)(row0 + 8) * DIM + col) = v1;
        }
    }
}

// ---------------------------------------------------------------------------
__global__ __launch_bounds__(256, 1)
void gemm_qkv_kernel(const float* __restrict__ bq,
                     const float* __restrict__ bk,
                     const float* __restrict__ bv)
{
    extern __shared__ __align__(16) char smem[];
    const int nb = blockIdx.x;
    const int mat = nb >> 3;
    const int n0 = (nb & 7) * GBN;
    const int m0 = blockIdx.y * GBM;

    const float* bias;
    float* C;
    int act;
    if (mat == 0)      { bias = bq; C = g_Q; act = 1; }
    else if (mat == 1) { bias = bk; C = g_K; act = 1; }
    else               { bias = bv; C = g_V; act = 0; }

    gemm_body(g_xh, g_xl, g_wh[mat], g_wl[mat], bias, C, m0, n0, act, smem);
}

__global__ __launch_bounds__(256, 1)
void gemm_o_kernel(const float* __restrict__ bias, float* __restrict__ C)
{
    extern __shared__ __align__(16) char smem[];
    gemm_body(g_ah, g_al, g_wh[3], g_wl[3], bias, C,
              blockIdx.y * GBM, blockIdx.x * GBN, 0, smem);
}

// ---------------------------------------------------------------------------
__global__ void zero_kv_kernel()
{
    const int i = blockIdx.x * 256 + threadIdx.x;
    if (i < BDIM * HEADS * HD * HD) g_KV[i] = 0.f;
    if (i < BDIM * HEADS * HD)      g_Ksum[i] = 0.f;
}

// ---------------------------------------------------------------------------
// KV[b,h,d,v] = sum_n K*V ; Ksum = sum_n K. f32x2 packed FMAs.
// ---------------------------------------------------------------------------
__global__ __launch_bounds__(256)
void kv_kernel(const float* __restrict__ K, const float* __restrict__ V)
{
    const int bh = blockIdx.x;
    const int seg = blockIdx.y;
    const int b = bh >> 4, h = bh & 15;
    const int tid = threadIdx.x;

    __shared__ __align__(16) float ks[8][64];
    __shared__ __align__(16) float vs[8][64];

    const int dq = tid >> 4;
    const int vq = tid & 15;
    unsigned long long acc2[4][2];
    #pragma unroll
    for (int a = 0; a < 4; a++) { acc2[a][0] = 0ull; acc2[a][1] = 0ull; }
    float ksacc = 0.f;

    const size_t base = ((size_t)b * NSEQ) * DIM + h * HD;
    const int row8 = tid >> 5;
    const int q = tid & 31;
    const bool isV = (q >= 16);
    const int c4 = (q & 15) * 4;

    const int nbeg = seg * (NSEQ / 8);
    const int nend = nbeg + (NSEQ / 8);

    for (int n0 = nbeg; n0 < nend; n0 += 8) {
        const size_t g = base + (size_t)(n0 + row8) * DIM + c4;
        float4 val = isV ? *(const float4*)(V + g) : *(const float4*)(K + g);
        float* dst = isV ? &vs[row8][c4] : &ks[row8][c4];
        *(float4*)dst = val;
        __syncthreads();
        #pragma unroll
        for (int i = 0; i < 8; i++) {
            const float4 kv = *(const float4*)&ks[i][dq * 4];
            const ulonglong2 vv = *(const ulonglong2*)&vs[i][vq * 4];
            unsigned long long k0 = pack2(kv.x), k1 = pack2(kv.y);
            unsigned long long k2 = pack2(kv.z), k3 = pack2(kv.w);
            ffma2(acc2[0][0], k0, vv.x); ffma2(acc2[0][1], k0, vv.y);
            ffma2(acc2[1][0], k1, vv.x); ffma2(acc2[1][1], k1, vv.y);
            ffma2(acc2[2][0], k2, vv.x); ffma2(acc2[2][1], k2, vv.y);
            ffma2(acc2[3][0], k3, vv.x); ffma2(acc2[3][1], k3, vv.y);
        }
        if (tid < 64) {
            #pragma unroll
            for (int i = 0; i < 8; i++) ksacc += ks[i][tid];
        }
        __syncthreads();
    }

    float* kvout = g_KV + bh * (HD * HD);
    #pragma unroll
    for (int a = 0; a < 4; a++) {
        float* row = &kvout[(dq * 4 + a) * HD + vq * 4];
        atomicAdd(row + 0, lo2(acc2[a][0]));
        atomicAdd(row + 1, hi2(acc2[a][0]));
        atomicAdd(row + 2, lo2(acc2[a][1]));
        atomicAdd(row + 3, hi2(acc2[a][1]));
    }
    if (tid < 64) atomicAdd(&g_Ksum[bh * HD + tid], ksacc);
}

// ---------------------------------------------------------------------------
// attn -> bf16 hi/lo splits. f32x2 packed FMAs.
// ---------------------------------------------------------------------------
__global__ __launch_bounds__(256)
void attn_kernel(const float* __restrict__ Q,
                 const float* __restrict__ stdp,
                 __nv_bfloat16* __restrict__ outh,
                 __nv_bfloat16* __restrict__ outl)
{
    const int bh = blockIdx.y;
    const int b = bh >> 4, h = bh & 15;
    const int n0 = blockIdx.x * 64;
    const int tid = threadIdx.x;

    __shared__ __align__(16) float qs[64][68];
    __shared__ __align__(16) float kvs[64][68];
    __shared__ float ksum_s[64];

    const size_t qbase = ((size_t)b * NSEQ + n0) * DIM + h * HD;
    #pragma unroll
    for (int i = 0; i < 4; i++) {
        const int slot = tid + i * 256;
        const int r = slot >> 4;
        const int c4 = (slot & 15) * 4;
        *(float4*)&qs[r][c4]  = *(const float4*)(Q + qbase + (size_t)r * DIM + c4);
        *(float4*)&kvs[r][c4] = *(const float4*)(g_KV + bh * (HD * HD) + r * HD + c4);
    }
    if (tid < 64) ksum_s[tid] = g_Ksum[bh * HD + tid];
    __syncthreads();

    const int r = tid >> 2;
    const int quad = tid & 3;
    unsigned long long acc2[8];
    #pragma unroll
    for (int j = 0; j < 8; j++) acc2[j] = 0ull;
    float den = 0.f;

    #pragma unroll 4
    for (int d = 0; d < 64; d++) {
        const float qv = qs[r][d];
        den += qv * ksum_s[d];
        const unsigned long long qp = pack2(qv);
        const ulonglong2 p0 = *(const ulonglong2*)&kvs[d][quad * 16 + 0];
        const ulonglong2 p1 = *(const ulonglong2*)&kvs[d][quad * 16 + 4];
        const ulonglong2 p2 = *(const ulonglong2*)&kvs[d][quad * 16 + 8];
        const ulonglong2 p3 = *(const ulonglong2*)&kvs[d][quad * 16 + 12];
        ffma2(acc2[0], qp, p0.x); ffma2(acc2[1], qp, p0.y);
        ffma2(acc2[2], qp, p1.x); ffma2(acc2[3], qp, p1.y);
        ffma2(acc2[4], qp, p2.x); ffma2(acc2[5], qp, p2.y);
        ffma2(acc2[6], qp, p3.x); ffma2(acc2[7], qp, p3.y);
    }

    const float sig = 1.f / (1.f + expf(-stdp[h]));
    const float scale = sig / (den + 1e-6f);

    const size_t obase = ((size_t)b * NSEQ + n0 + r) * DIM + h * HD + quad * 16;
    #pragma unroll
    for (int j = 0; j < 8; j += 2) {
        __nv_bfloat162 hh[2], ll[2];
        #pragma unroll
        for (int e = 0; e < 2; e++) {
            const unsigned long long v = acc2[j + e];
            float v0 = lo2(v) * scale;
            float v1 = hi2(v) * scale;
            __nv_bfloat16 h0 = __float2bfloat16_rn(v0);
            __nv_bfloat16 h1 = __float2bfloat16_rn(v1);
            __nv_bfloat16 l0 = __float2bfloat16_rn(v0 - __bfloat162float(h0));
            __nv_bfloat16 l1 = __float2bfloat16_rn(v1 - __bfloat162float(h1));
            hh[e] = __halves2bfloat162(h0, h1);
            ll[e] = __halves2bfloat162(l0, l1);
        }
        *(__nv_bfloat162*)(outh + obase + j * 2)     = hh[0];
        *(__nv_bfloat162*)(outh + obase + j * 2 + 2) = hh[1];
        *(__nv_bfloat162*)(outl + obase + j * 2)     = ll[0];
        *(__nv_bfloat162*)(outl + obase + j * 2 + 2) = ll[1];
    }
}

// ---------------------------------------------------------------------------
__global__ void tail_kernel(const float* __restrict__ stdp,
                            float* __restrict__ out, int extra)
{
    const int i = threadIdx.x + blockIdx.x * blockDim.x;
    if (i < extra) {
        out[(size_t)MTOT * DIM + i] = (i < HEADS) ? stdp[i] : 0.f;
    }
}

// ---------------------------------------------------------------------------
extern "C" void kernel_launch(void* const* d_in, const int* in_sizes, int n_in,
                              void* d_out, int out_size)
{
    const float* x    = (const float*)d_in[0];
    const float* Wq   = (const float*)d_in[1];
    const float* bq   = (const float*)d_in[2];
    const float* Wk   = (const float*)d_in[3];
    const float* bk   = (const float*)d_in[4];
    const float* Wv   = (const float*)d_in[5];
    const float* bv   = (const float*)d_in[6];
    const float* Wo   = (const float*)d_in[7];
    const float* bo   = (const float*)d_in[8];
    const float* stdp = (const float*)d_in[9];
    float* out = (float*)d_out;

    float *pQ, *pK, *pV;
    cudaGetSymbolAddress((void**)&pQ, g_Q);
    cudaGetSymbolAddress((void**)&pK, g_K);
    cudaGetSymbolAddress((void**)&pV, g_V);
    __nv_bfloat16 *ah, *al;
    cudaGetSymbolAddress((void**)&ah, g_ah);
    cudaGetSymbolAddress((void**)&al, g_al);

    cudaFuncSetAttribute(gemm_qkv_kernel,
                         cudaFuncAttributeMaxDynamicSharedMemorySize, SMEMG);
    cudaFuncSetAttribute(gemm_o_kernel,
                         cudaFuncAttributeMaxDynamicSharedMemorySize, SMEMG);

    const int nx4 = MTOT * DIM / 4;

    // launch order: index 3 = gemm_qkv (ncu capture slot)
    wsplit_kernel<<<4096, 256>>>(Wq, Wk, Wv, Wo);                       // 0
    xsplit_kernel<<<nx4 / 256, 256>>>(x);                               // 1
    zero_kv_kernel<<<(BDIM * HEADS * HD * HD + 255) / 256, 256>>>();    // 2
    gemm_qkv_kernel<<<dim3(24, MTOT / GBM), 256, SMEMG>>>(bq, bk, bv);  // 3
    kv_kernel<<<dim3(BDIM * HEADS, 8), 256>>>(pK, pV);                  // 4
    attn_kernel<<<dim3(NSEQ / 64, BDIM * HEADS), 256>>>(pQ, stdp, ah, al); // 5
    gemm_o_kernel<<<dim3(DIM / GBN, MTOT / GBM), 256, SMEMG>>>(bo, out);   // 6

    const int extra = out_size - MTOT * DIM;
    if (extra > 0) {
        tail_kernel<<<(extra + 255) / 256, 256>>>(stdp, out, extra);    // 7
    }
}

// round 8
// speedup vs baseline: 2.1573x; 1.0203x over previous
#include <cuda_runtime.h>
#include <cuda_bf16.h>
#include <math.h>
#include <stdint.h>

// ---------------------------------------------------------------------------
// SpikeAttention (linear attention, ELU+1 feature map)
//   B=4, N=4096, DIM=1024, HEADS=16, HEAD_DIM=64
// Round 8: GEMM goes to 512 threads / 16 warps per CTA (32x32 warp tile) to
// fix the occupancy bottleneck (occ 12.5% -> 25%, tensor 52% -> target 80%).
// 3-term bf16 mma.sync split GEMMs (A*B ~= Ah*Bh + Al*Bh + Ah*Bl).
// ---------------------------------------------------------------------------

#define BDIM  4
#define NSEQ  4096
#define DIM   1024
#define HEADS 16
#define HD    64
#define MTOT  (BDIM * NSEQ)          // 16384

__device__ float g_Q[(size_t)MTOT * DIM];
__device__ float g_K[(size_t)MTOT * DIM];
__device__ float g_V[(size_t)MTOT * DIM];
__device__ float g_KV[BDIM * HEADS * HD * HD];
__device__ float g_Ksum[BDIM * HEADS * HD];

__device__ __align__(16) __nv_bfloat16 g_xh[(size_t)MTOT * DIM];
__device__ __align__(16) __nv_bfloat16 g_xl[(size_t)MTOT * DIM];
__device__ __align__(16) __nv_bfloat16 g_ah[(size_t)MTOT * DIM];
__device__ __align__(16) __nv_bfloat16 g_al[(size_t)MTOT * DIM];
__device__ __align__(16) __nv_bfloat16 g_wh[4][DIM * DIM];   // q,k,v,o hi
__device__ __align__(16) __nv_bfloat16 g_wl[4][DIM * DIM];   // q,k,v,o lo

// ---- packed f32x2 helpers -------------------------------------------------
__device__ __forceinline__ unsigned long long pack2(float x) {
    unsigned long long r;
    unsigned u = __float_as_uint(x);
    asm("mov.b64 %0, {%1, %1};" : "=l"(r) : "r"(u));
    return r;
}
__device__ __forceinline__ void ffma2(unsigned long long& d,
                                      unsigned long long a,
                                      unsigned long long b) {
    asm("fma.rn.f32x2 %0, %1, %2, %0;" : "+l"(d) : "l"(a), "l"(b));
}
__device__ __forceinline__ float lo2(unsigned long long v) {
    return __uint_as_float((unsigned)(v & 0xffffffffull));
}
__device__ __forceinline__ float hi2(unsigned long long v) {
    return __uint_as_float((unsigned)(v >> 32));
}

// ---------------------------------------------------------------------------
__device__ __forceinline__ void split4(const float* __restrict__ src,
                                       __nv_bfloat16* __restrict__ hi,
                                       __nv_bfloat16* __restrict__ lo, int i)
{
    float4 f = ((const float4*)src)[i];
    __nv_bfloat16 h0 = __float2bfloat16_rn(f.x);
    __nv_bfloat16 h1 = __float2bfloat16_rn(f.y);
    __nv_bfloat16 h2 = __float2bfloat16_rn(f.z);
    __nv_bfloat16 h3 = __float2bfloat16_rn(f.w);
    __nv_bfloat16 l0 = __float2bfloat16_rn(f.x - __bfloat162float(h0));
    __nv_bfloat16 l1 = __float2bfloat16_rn(f.y - __bfloat162float(h1));
    __nv_bfloat16 l2 = __float2bfloat16_rn(f.z - __bfloat162float(h2));
    __nv_bfloat16 l3 = __float2bfloat16_rn(f.w - __bfloat162float(h3));
    ((__nv_bfloat162*)hi)[2 * i + 0] = __halves2bfloat162(h0, h1);
    ((__nv_bfloat162*)hi)[2 * i + 1] = __halves2bfloat162(h2, h3);
    ((__nv_bfloat162*)lo)[2 * i + 0] = __halves2bfloat162(l0, l1);
    ((__nv_bfloat162*)lo)[2 * i + 1] = __halves2bfloat162(l2, l3);
}

__global__ __launch_bounds__(256)
void wsplit_kernel(const float* __restrict__ Wq, const float* __restrict__ Wk,
                   const float* __restrict__ Wv, const float* __restrict__ Wo)
{
    const int mat = blockIdx.x >> 10;
    const int i = (blockIdx.x & 1023) * 256 + threadIdx.x;
    const float* src = (mat == 0) ? Wq : (mat == 1) ? Wk : (mat == 2) ? Wv : Wo;
    split4(src, g_wh[mat], g_wl[mat], i);
}

__global__ __launch_bounds__(256)
void xsplit_kernel(const float* __restrict__ x)
{
    const int i = blockIdx.x * 256 + threadIdx.x;
    split4(x, g_xh, g_xl, i);
}

// ===========================================================================
// GEMM core: 128x128 CTA tile, GBK=64, 3-stage cp.async, 512 threads,
// 16 warps in a 4x4 grid, each warp owns a 32x32 sub-tile.
// ===========================================================================
#define GBM 128
#define GBN 128
#define GBK 64
#define NCHUNK (DIM / GBK)           // 16
#define RS 144
#define TILE_B (128 * RS)
#define STAGE_B (4 * TILE_B)
#define GSTAGES 3
#define SMEMG (GSTAGES * STAGE_B)    // 221184
#define GTHREADS 512

__device__ __forceinline__ uint32_t smem_u32(const void* p) {
    uint32_t a;
    asm("{ .reg .u64 t; cvta.to.shared.u64 t, %1; cvt.u32.u64 %0, t; }"
        : "=r"(a) : "l"(p));
    return a;
}
__device__ __forceinline__ void cp16(uint32_t dst, const void* src) {
    asm volatile("cp.async.cg.shared.global [%0], [%1], 16;"
                 :: "r"(dst), "l"(src));
}
__device__ __forceinline__ void ldm4(uint32_t* r, uint32_t addr) {
    asm volatile("ldmatrix.sync.aligned.m8n8.x4.shared.b16 {%0,%1,%2,%3}, [%4];"
                 : "=r"(r[0]), "=r"(r[1]), "=r"(r[2]), "=r"(r[3]) : "r"(addr));
}
__device__ __forceinline__ void mma_bf16(float* c, const uint32_t* a,
                                         const uint32_t* b) {
    asm volatile(
        "mma.sync.aligned.m16n8k16.row.col.f32.bf16.bf16.f32 "
        "{%0,%1,%2,%3}, {%4,%5,%6,%7}, {%8,%9}, {%0,%1,%2,%3};"
        : "+f"(c[0]), "+f"(c[1]), "+f"(c[2]), "+f"(c[3])
        : "r"(a[0]), "r"(a[1]), "r"(a[2]), "r"(a[3]), "r"(b[0]), "r"(b[1]));
}

__device__ __forceinline__
void gemm_body(const __nv_bfloat16* __restrict__ Ah,
               const __nv_bfloat16* __restrict__ Al,
               const __nv_bfloat16* __restrict__ Bh,
               const __nv_bfloat16* __restrict__ Bl,
               const float* __restrict__ bias,
               float* __restrict__ C,
               int m0, int n0, int act, char* smem)
{
    const uint32_t sbase = smem_u32(smem);
    const int tid = threadIdx.x;
    const int lane = tid & 31;
    const int wid = tid >> 5;        // 0..15
    const int wm = wid & 3;          // 4 warps over M (32 rows each)
    const int wn = wid >> 2;         // 4 warps over N (32 cols each)

    // stage loader: 4096 x 16B chunks, 8 per thread (512 threads)
    auto load_stage = [&](int ck, int slot) {
        const uint32_t sb = sbase + slot * STAGE_B;
        const int kofs = ck * GBK;
        #pragma unroll
        for (int i = 0; i < 8; i++) {
            const int id = tid + i * GTHREADS;   // 0..4095
            const int tile = id >> 10;           // 0:Ah 1:Al 2:Bh 3:Bl
            const int r = (id >> 3) & 127;
            const int c = id & 7;
            const uint32_t dst = sb + tile * TILE_B + r * RS + c * 16;
            const __nv_bfloat16* src;
            if (tile == 0)      src = Ah + (size_t)(m0 + r) * DIM + kofs + c * 8;
            else if (tile == 1) src = Al + (size_t)(m0 + r) * DIM + kofs + c * 8;
            else if (tile == 2) src = Bh + (size_t)(n0 + r) * DIM + kofs + c * 8;
            else                src = Bl + (size_t)(n0 + r) * DIM + kofs + c * 8;
            cp16(dst, src);
        }
    };

    load_stage(0, 0);
    asm volatile("cp.async.commit_group;");
    load_stage(1, 1);
    asm volatile("cp.async.commit_group;");

    float acc[2][4][4];
    #pragma unroll
    for (int mf = 0; mf < 2; mf++)
        #pragma unroll
        for (int nf = 0; nf < 4; nf++)
            #pragma unroll
            for (int e = 0; e < 4; e++) acc[mf][nf][e] = 0.f;

    const int rl = lane & 15;
    const int cb16 = (lane >> 4) << 4;

    for (int ck = 0; ck < NCHUNK; ck++) {
        asm volatile("cp.async.wait_group 1;");
        __syncthreads();
        if (ck + 2 < NCHUNK) load_stage(ck + 2, (ck + 2) % GSTAGES);
        asm volatile("cp.async.commit_group;");

        const uint32_t sb = sbase + (ck % GSTAGES) * STAGE_B;
        #pragma unroll
        for (int k16 = 0; k16 < 4; k16++) {
            const int cb = k16 * 32 + cb16;
            uint32_t ah[2][4], al[2][4], bh[4][2], bl[4][2];
            #pragma unroll
            for (int mf = 0; mf < 2; mf++) {
                const uint32_t ra = (wm * 32 + mf * 16 + rl) * RS + cb;
                ldm4(ah[mf], sb + ra);
                ldm4(al[mf], sb + TILE_B + ra);
            }
            #pragma unroll
            for (int p = 0; p < 2; p++) {   // 2 x (16 cols) = 32 cols
                const uint32_t rb = (wn * 32 + p * 16 + rl) * RS + cb;
                uint32_t t[4];
                ldm4(t, sb + 2 * TILE_B + rb);
                bh[2 * p][0] = t[0]; bh[2 * p][1] = t[2];
                bh[2 * p + 1][0] = t[1]; bh[2 * p + 1][1] = t[3];
                ldm4(t, sb + 3 * TILE_B + rb);
                bl[2 * p][0] = t[0]; bl[2 * p][1] = t[2];
                bl[2 * p + 1][0] = t[1]; bl[2 * p + 1][1] = t[3];
            }
            #pragma unroll
            for (int mf = 0; mf < 2; mf++)
                #pragma unroll
                for (int nf = 0; nf < 4; nf++)
                    mma_bf16(acc[mf][nf], ah[mf], bh[nf]);
            #pragma unroll
            for (int mf = 0; mf < 2; mf++)
                #pragma unroll
                for (int nf = 0; nf < 4; nf++)
                    mma_bf16(acc[mf][nf], al[mf], bh[nf]);
            #pragma unroll
            for (int mf = 0; mf < 2; mf++)
                #pragma unroll
                for (int nf = 0; nf < 4; nf++)
                    mma_bf16(acc[mf][nf], ah[mf], bl[nf]);
        }
    }

    const int gid = lane >> 2;
    const int cq = (lane & 3) * 2;
    #pragma unroll
    for (int mf = 0; mf < 2; mf++) {
        const int row0 = m0 + wm * 32 + mf * 16 + gid;
        #pragma unroll
        for (int nf = 0; nf < 4; nf++) {
            const int col = n0 + wn * 32 + nf * 8 + cq;
            const float2 bv = *(const float2*)(bias + col);
            float2 v0, v1;
            v0.x = acc[mf][nf][0] + bv.x;
            v0.y = acc[mf][nf][1] + bv.y;
            v1.x = acc[mf][nf][2] + bv.x;
            v1.y = acc[mf][nf][3] + bv.y;
            if (act) {
                v0.x = (v0.x > 0.f) ? v0.x + 1.f : __expf(v0.x);
                v0.y = (v0.y > 0.f) ? v0.y + 1.f : __expf(v0.y);
                v1.x = (v1.x > 0.f) ? v1.x + 1.f : __expf(v1.x);
                v1.y = (v1.y > 0.f) ? v1.y + 1.f : __expf(v1.y);
            }
            *(float2*)(C + (size_t)row0 * DIM + col) = v0;
            *(float2*)(C + (size_t)(row0 + 8) * DIM + col) = v1;
        }
    }
}

// ---------------------------------------------------------------------------
__global__ __launch_bounds__(GTHREADS, 1)
void gemm_qkv_kernel(const float* __restrict__ bq,
                     const float* __restrict__ bk,
                     const float* __restrict__ bv)
{
    extern __shared__ __align__(16) char smem[];
    const int nb = blockIdx.x;
    const int mat = nb >> 3;
    const int n0 = (nb & 7) * GBN;
    const int m0 = blockIdx.y * GBM;

    const float* bias;
    float* C;
    int act;
    if (mat == 0)      { bias = bq; C = g_Q; act = 1; }
    else if (mat == 1) { bias = bk; C = g_K; act = 1; }
    else               { bias = bv; C = g_V; act = 0; }

    gemm_body(g_xh, g_xl, g_wh[mat], g_wl[mat], bias, C, m0, n0, act, smem);
}

__global__ __launch_bounds__(GTHREADS, 1)
void gemm_o_kernel(const float* __restrict__ bias, float* __restrict__ C)
{
    extern __shared__ __align__(16) char smem[];
    gemm_body(g_ah, g_al, g_wh[3], g_wl[3], bias, C,
              blockIdx.y * GBM, blockIdx.x * GBN, 0, smem);
}

// ---------------------------------------------------------------------------
__global__ void zero_kv_kernel()
{
    const int i = blockIdx.x * 256 + threadIdx.x;
    if (i < BDIM * HEADS * HD * HD) g_KV[i] = 0.f;
    if (i < BDIM * HEADS * HD)      g_Ksum[i] = 0.f;
}

// ---------------------------------------------------------------------------
// KV[b,h,d,v] = sum_n K*V ; Ksum = sum_n K. f32x2 packed FMAs.
// ---------------------------------------------------------------------------
__global__ __launch_bounds__(256)
void kv_kernel(const float* __restrict__ K, const float* __restrict__ V)
{
    const int bh = blockIdx.x;
    const int seg = blockIdx.y;
    const int b = bh >> 4, h = bh & 15;
    const int tid = threadIdx.x;

    __shared__ __align__(16) float ks[8][64];
    __shared__ __align__(16) float vs[8][64];

    const int dq = tid >> 4;
    const int vq = tid & 15;
    unsigned long long acc2[4][2];
    #pragma unroll
    for (int a = 0; a < 4; a++) { acc2[a][0] = 0ull; acc2[a][1] = 0ull; }
    float ksacc = 0.f;

    const size_t base = ((size_t)b * NSEQ) * DIM + h * HD;
    const int row8 = tid >> 5;
    const int q = tid & 31;
    const bool isV = (q >= 16);
    const int c4 = (q & 15) * 4;

    const int nbeg = seg * (NSEQ / 8);
    const int nend = nbeg + (NSEQ / 8);

    for (int n0 = nbeg; n0 < nend; n0 += 8) {
        const size_t g = base + (size_t)(n0 + row8) * DIM + c4;
        float4 val = isV ? *(const float4*)(V + g) : *(const float4*)(K + g);
        float* dst = isV ? &vs[row8][c4] : &ks[row8][c4];
        *(float4*)dst = val;
        __syncthreads();
        #pragma unroll
        for (int i = 0; i < 8; i++) {
            const float4 kv = *(const float4*)&ks[i][dq * 4];
            const ulonglong2 vv = *(const ulonglong2*)&vs[i][vq * 4];
            unsigned long long k0 = pack2(kv.x), k1 = pack2(kv.y);
            unsigned long long k2 = pack2(kv.z), k3 = pack2(kv.w);
            ffma2(acc2[0][0], k0, vv.x); ffma2(acc2[0][1], k0, vv.y);
            ffma2(acc2[1][0], k1, vv.x); ffma2(acc2[1][1], k1, vv.y);
            ffma2(acc2[2][0], k2, vv.x); ffma2(acc2[2][1], k2, vv.y);
            ffma2(acc2[3][0], k3, vv.x); ffma2(acc2[3][1], k3, vv.y);
        }
        if (tid < 64) {
            #pragma unroll
            for (int i = 0; i < 8; i++) ksacc += ks[i][tid];
        }
        __syncthreads();
    }

    float* kvout = g_KV + bh * (HD * HD);
    #pragma unroll
    for (int a = 0; a < 4; a++) {
        float* row = &kvout[(dq * 4 + a) * HD + vq * 4];
        atomicAdd(row + 0, lo2(acc2[a][0]));
        atomicAdd(row + 1, hi2(acc2[a][0]));
        atomicAdd(row + 2, lo2(acc2[a][1]));
        atomicAdd(row + 3, hi2(acc2[a][1]));
    }
    if (tid < 64) atomicAdd(&g_Ksum[bh * HD + tid], ksacc);
}

// ---------------------------------------------------------------------------
// attn -> bf16 hi/lo splits. f32x2 packed FMAs.
// ---------------------------------------------------------------------------
__global__ __launch_bounds__(256)
void attn_kernel(const float* __restrict__ Q,
                 const float* __restrict__ stdp,
                 __nv_bfloat16* __restrict__ outh,
                 __nv_bfloat16* __restrict__ outl)
{
    const int bh = blockIdx.y;
    const int b = bh >> 4, h = bh & 15;
    const int n0 = blockIdx.x * 64;
    const int tid = threadIdx.x;

    __shared__ __align__(16) float qs[64][68];
    __shared__ __align__(16) float kvs[64][68];
    __shared__ float ksum_s[64];

    const size_t qbase = ((size_t)b * NSEQ + n0) * DIM + h * HD;
    #pragma unroll
    for (int i = 0; i < 4; i++) {
        const int slot = tid + i * 256;
        const int r = slot >> 4;
        const int c4 = (slot & 15) * 4;
        *(float4*)&qs[r][c4]  = *(const float4*)(Q + qbase + (size_t)r * DIM + c4);
        *(float4*)&kvs[r][c4] = *(const float4*)(g_KV + bh * (HD * HD) + r * HD + c4);
    }
    if (tid < 64) ksum_s[tid] = g_Ksum[bh * HD + tid];
    __syncthreads();

    const int r = tid >> 2;
    const int quad = tid & 3;
    unsigned long long acc2[8];
    #pragma unroll
    for (int j = 0; j < 8; j++) acc2[j] = 0ull;
    float den = 0.f;

    #pragma unroll 4
    for (int d = 0; d < 64; d++) {
        const float qv = qs[r][d];
        den += qv * ksum_s[d];
        const unsigned long long qp = pack2(qv);
        const ulonglong2 p0 = *(const ulonglong2*)&kvs[d][quad * 16 + 0];
        const ulonglong2 p1 = *(const ulonglong2*)&kvs[d][quad * 16 + 4];
        const ulonglong2 p2 = *(const ulonglong2*)&kvs[d][quad * 16 + 8];
        const ulonglong2 p3 = *(const ulonglong2*)&kvs[d][quad * 16 + 12];
        ffma2(acc2[0], qp, p0.x); ffma2(acc2[1], qp, p0.y);
        ffma2(acc2[2], qp, p1.x); ffma2(acc2[3], qp, p1.y);
        ffma2(acc2[4], qp, p2.x); ffma2(acc2[5], qp, p2.y);
        ffma2(acc2[6], qp, p3.x); ffma2(acc2[7], qp, p3.y);
    }

    const float sig = 1.f / (1.f + expf(-stdp[h]));
    const float scale = sig / (den + 1e-6f);

    const size_t obase = ((size_t)b * NSEQ + n0 + r) * DIM + h * HD + quad * 16;
    #pragma unroll
    for (int j = 0; j < 8; j += 2) {
        __nv_bfloat162 hh[2], ll[2];
        #pragma unroll
        for (int e = 0; e < 2; e++) {
            const unsigned long long v = acc2[j + e];
            float v0 = lo2(v) * scale;
            float v1 = hi2(v) * scale;
            __nv_bfloat16 h0 = __float2bfloat16_rn(v0);
            __nv_bfloat16 h1 = __float2bfloat16_rn(v1);
            __nv_bfloat16 l0 = __float2bfloat16_rn(v0 - __bfloat162float(h0));
            __nv_bfloat16 l1 = __float2bfloat16_rn(v1 - __bfloat162float(h1));
            hh[e] = __halves2bfloat162(h0, h1);
            ll[e] = __halves2bfloat162(l0, l1);
        }
        *(__nv_bfloat162*)(outh + obase + j * 2)     = hh[0];
        *(__nv_bfloat162*)(outh + obase + j * 2 + 2) = hh[1];
        *(__nv_bfloat162*)(outl + obase + j * 2)     = ll[0];
        *(__nv_bfloat162*)(outl + obase + j * 2 + 2) = ll[1];
    }
}

// ---------------------------------------------------------------------------
__global__ void tail_kernel(const float* __restrict__ stdp,
                            float* __restrict__ out, int extra)
{
    const int i = threadIdx.x + blockIdx.x * blockDim.x;
    if (i < extra) {
        out[(size_t)MTOT * DIM + i] = (i < HEADS) ? stdp[i] : 0.f;
    }
}

// ---------------------------------------------------------------------------
extern "C" void kernel_launch(void* const* d_in, const int* in_sizes, int n_in,
                              void* d_out, int out_size)
{
    const float* x    = (const float*)d_in[0];
    const float* Wq   = (const float*)d_in[1];
    const float* bq   = (const float*)d_in[2];
    const float* Wk   = (const float*)d_in[3];
    const float* bk   = (const float*)d_in[4];
    const float* Wv   = (const float*)d_in[5];
    const float* bv   = (const float*)d_in[6];
    const float* Wo   = (const float*)d_in[7];
    const float* bo   = (const float*)d_in[8];
    const float* stdp = (const float*)d_in[9];
    float* out = (float*)d_out;

    float *pQ, *pK, *pV;
    cudaGetSymbolAddress((void**)&pQ, g_Q);
    cudaGetSymbolAddress((void**)&pK, g_K);
    cudaGetSymbolAddress((void**)&pV, g_V);
    __nv_bfloat16 *ah, *al;
    cudaGetSymbolAddress((void**)&ah, g_ah);
    cudaGetSymbolAddress((void**)&al, g_al);

    cudaFuncSetAttribute(gemm_qkv_kernel,
                         cudaFuncAttributeMaxDynamicSharedMemorySize, SMEMG);
    cudaFuncSetAttribute(gemm_o_kernel,
                         cudaFuncAttributeMaxDynamicSharedMemorySize, SMEMG);

    const int nx4 = MTOT * DIM / 4;

    // launch order: index 3 = gemm_qkv (ncu capture slot)
    wsplit_kernel<<<4096, 256>>>(Wq, Wk, Wv, Wo);                       // 0
    xsplit_kernel<<<nx4 / 256, 256>>>(x);                               // 1
    zero_kv_kernel<<<(BDIM * HEADS * HD * HD + 255) / 256, 256>>>();    // 2
    gemm_qkv_kernel<<<dim3(24, MTOT / GBM), GTHREADS, SMEMG>>>(bq, bk, bv); // 3
    kv_kernel<<<dim3(BDIM * HEADS, 8), 256>>>(pK, pV);                  // 4
    attn_kernel<<<dim3(NSEQ / 64, BDIM * HEADS), 256>>>(pQ, stdp, ah, al); // 5
    gemm_o_kernel<<<dim3(DIM / GBN, MTOT / GBM), GTHREADS, SMEMG>>>(bo, out); // 6

    const int extra = out_size - MTOT * DIM;
    if (extra > 0) {
        tail_kernel<<<(extra + 255) / 256, 256>>>(stdp, out, extra);    // 7
    }
}

// round 9
// speedup vs baseline: 2.8860x; 1.3378x over previous
#include <cuda_runtime.h>
#include <cuda_fp16.h>
#include <math.h>
#include <stdint.h>

// ---------------------------------------------------------------------------
// SpikeAttention (linear attention, ELU+1 feature map)
//   B=4, N=4096, DIM=1024, HEADS=16, HEAD_DIM=64
// Round 9: 2-term fp16 split GEMM with scaled weight residual:
//   C = A_fp16 * Wh  +  (A_fp16 * Wl) * 2^-11,   Wl = fp16((W - Wh) * 2048)
// (residual scaling keeps Wl out of fp16-subnormal range).
// Separate fp32 accumulators per term, merged in epilogue. -33% MMA work.
// ---------------------------------------------------------------------------

#define BDIM  4
#define NSEQ  4096
#define DIM   1024
#define HEADS 16
#define HD    64
#define MTOT  (BDIM * NSEQ)          // 16384

__device__ float g_Q[(size_t)MTOT * DIM];
__device__ float g_K[(size_t)MTOT * DIM];
__device__ float g_V[(size_t)MTOT * DIM];
__device__ float g_KV[BDIM * HEADS * HD * HD];
__device__ float g_Ksum[BDIM * HEADS * HD];

__device__ __align__(16) __half g_xh[(size_t)MTOT * DIM];   // fp16(x)
__device__ __align__(16) __half g_ah[(size_t)MTOT * DIM];   // fp16(attn)
__device__ __align__(16) __half g_wh[4][DIM * DIM];          // q,k,v,o hi
__device__ __align__(16) __half g_wl[4][DIM * DIM];          // q,k,v,o lo*2048

// ---- packed f32x2 helpers -------------------------------------------------
__device__ __forceinline__ unsigned long long pack2(float x) {
    unsigned long long r;
    unsigned u = __float_as_uint(x);
    asm("mov.b64 %0, {%1, %1};" : "=l"(r) : "r"(u));
    return r;
}
__device__ __forceinline__ void ffma2(unsigned long long& d,
                                      unsigned long long a,
                                      unsigned long long b) {
    asm("fma.rn.f32x2 %0, %1, %2, %0;" : "+l"(d) : "l"(a), "l"(b));
}
__device__ __forceinline__ float lo2(unsigned long long v) {
    return __uint_as_float((unsigned)(v & 0xffffffffull));
}
__device__ __forceinline__ float hi2(unsigned long long v) {
    return __uint_as_float((unsigned)(v >> 32));
}

// ---------------------------------------------------------------------------
// weight split: Wh = fp16(w), Wl = fp16((w - Wh) * 2048)
// all four matrices in one launch: grid.x = 4096, matrix = bid>>10
// ---------------------------------------------------------------------------
__global__ __launch_bounds__(256)
void wsplit_kernel(const float* __restrict__ Wq, const float* __restrict__ Wk,
                   const float* __restrict__ Wv, const float* __restrict__ Wo)
{
    const int mat = blockIdx.x >> 10;
    const int i = (blockIdx.x & 1023) * 256 + threadIdx.x;
    const float* src = (mat == 0) ? Wq : (mat == 1) ? Wk : (mat == 2) ? Wv : Wo;
    float4 f = ((const float4*)src)[i];
    __half h0 = __float2half_rn(f.x);
    __half h1 = __float2half_rn(f.y);
    __half h2 = __float2half_rn(f.z);
    __half h3 = __float2half_rn(f.w);
    __half l0 = __float2half_rn((f.x - __half2float(h0)) * 2048.0f);
    __half l1 = __float2half_rn((f.y - __half2float(h1)) * 2048.0f);
    __half l2 = __float2half_rn((f.z - __half2float(h2)) * 2048.0f);
    __half l3 = __float2half_rn((f.w - __half2float(h3)) * 2048.0f);
    ((__half2*)g_wh[mat])[2 * i + 0] = __halves2half2(h0, h1);
    ((__half2*)g_wh[mat])[2 * i + 1] = __halves2half2(h2, h3);
    ((__half2*)g_wl[mat])[2 * i + 0] = __halves2half2(l0, l1);
    ((__half2*)g_wl[mat])[2 * i + 1] = __halves2half2(l2, l3);
}

// x -> fp16 (no split needed on the activation side)
__global__ __launch_bounds__(256)
void xconv_kernel(const float* __restrict__ x)
{
    const int i = blockIdx.x * 256 + threadIdx.x;
    float4 f = ((const float4*)x)[i];
    ((__half2*)g_xh)[2 * i + 0] = __halves2half2(__float2half_rn(f.x),
                                                 __float2half_rn(f.y));
    ((__half2*)g_xh)[2 * i + 1] = __halves2half2(__float2half_rn(f.z),
                                                 __float2half_rn(f.w));
}

// ===========================================================================
// GEMM core: 128x128 CTA tile, GBK=64, 4-stage cp.async, 512 threads,
// 16 warps (4x4), each warp owns 32x32. 3 smem tiles/stage: A, Wh, Wl.
// ===========================================================================
#define GBM 128
#define GBN 128
#define GBK 64
#define NCHUNK (DIM / GBK)           // 16
#define RS 144
#define TILE_B (128 * RS)            // 18432
#define STAGE_B (3 * TILE_B)         // 55296
#define GSTAGES 4
#define SMEMG (GSTAGES * STAGE_B)    // 221184
#define GTHREADS 512

__device__ __forceinline__ uint32_t smem_u32(const void* p) {
    uint32_t a;
    asm("{ .reg .u64 t; cvta.to.shared.u64 t, %1; cvt.u32.u64 %0, t; }"
        : "=r"(a) : "l"(p));
    return a;
}
__device__ __forceinline__ void cp16(uint32_t dst, const void* src) {
    asm volatile("cp.async.cg.shared.global [%0], [%1], 16;"
                 :: "r"(dst), "l"(src));
}
__device__ __forceinline__ void ldm4(uint32_t* r, uint32_t addr) {
    asm volatile("ldmatrix.sync.aligned.m8n8.x4.shared.b16 {%0,%1,%2,%3}, [%4];"
                 : "=r"(r[0]), "=r"(r[1]), "=r"(r[2]), "=r"(r[3]) : "r"(addr));
}
__device__ __forceinline__ void mma_f16(float* c, const uint32_t* a,
                                        const uint32_t* b) {
    asm volatile(
        "mma.sync.aligned.m16n8k16.row.col.f32.f16.f16.f32 "
        "{%0,%1,%2,%3}, {%4,%5,%6,%7}, {%8,%9}, {%0,%1,%2,%3};"
        : "+f"(c[0]), "+f"(c[1]), "+f"(c[2]), "+f"(c[3])
        : "r"(a[0]), "r"(a[1]), "r"(a[2]), "r"(a[3]), "r"(b[0]), "r"(b[1]));
}

__device__ __forceinline__
void gemm_body(const __half* __restrict__ A,
               const __half* __restrict__ Wh,
               const __half* __restrict__ Wl,
               const float* __restrict__ bias,
               float* __restrict__ C,
               int m0, int n0, int act, char* smem)
{
    const uint32_t sbase = smem_u32(smem);
    const int tid = threadIdx.x;
    const int lane = tid & 31;
    const int wid = tid >> 5;        // 0..15
    const int wm = wid & 3;          // 4 warps over M
    const int wn = wid >> 2;         // 4 warps over N

    // stage loader: 3072 x 16B granules, 6 per thread
    auto load_stage = [&](int ck, int slot) {
        const uint32_t sb = sbase + slot * STAGE_B;
        const int kofs = ck * GBK;
        #pragma unroll
        for (int i = 0; i < 6; i++) {
            const int id = tid + i * GTHREADS;   // 0..3071
            const int tile = id >> 10;           // 0:A 1:Wh 2:Wl
            const int r = (id >> 3) & 127;
            const int c = id & 7;
            const uint32_t dst = sb + tile * TILE_B + r * RS + c * 16;
            const __half* src;
            if (tile == 0)      src = A  + (size_t)(m0 + r) * DIM + kofs + c * 8;
            else if (tile == 1) src = Wh + (size_t)(n0 + r) * DIM + kofs + c * 8;
            else                src = Wl + (size_t)(n0 + r) * DIM + kofs + c * 8;
            cp16(dst, src);
        }
    };

    load_stage(0, 0);
    asm volatile("cp.async.commit_group;");
    load_stage(1, 1);
    asm volatile("cp.async.commit_group;");
    load_stage(2, 2);
    asm volatile("cp.async.commit_group;");

    float accm[2][4][4], accc[2][4][4];
    #pragma unroll
    for (int mf = 0; mf < 2; mf++)
        #pragma unroll
        for (int nf = 0; nf < 4; nf++)
            #pragma unroll
            for (int e = 0; e < 4; e++) { accm[mf][nf][e] = 0.f; accc[mf][nf][e] = 0.f; }

    const int rl = lane & 15;
    const int cb16 = (lane >> 4) << 4;

    for (int ck = 0; ck < NCHUNK; ck++) {
        asm volatile("cp.async.wait_group 2;");
        __syncthreads();
        if (ck + 3 < NCHUNK) load_stage(ck + 3, (ck + 3) & (GSTAGES - 1));
        asm volatile("cp.async.commit_group;");

        const uint32_t sb = sbase + (ck & (GSTAGES - 1)) * STAGE_B;
        #pragma unroll
        for (int k16 = 0; k16 < 4; k16++) {
            const int cb = k16 * 32 + cb16;
            uint32_t ar[2][4], bh[4][2], bl[4][2];
            #pragma unroll
            for (int mf = 0; mf < 2; mf++) {
                const uint32_t ra = (wm * 32 + mf * 16 + rl) * RS + cb;
                ldm4(ar[mf], sb + ra);
            }
            #pragma unroll
            for (int p = 0; p < 2; p++) {
                const uint32_t rb = (wn * 32 + p * 16 + rl) * RS + cb;
                uint32_t t[4];
                ldm4(t, sb + TILE_B + rb);
                bh[2 * p][0] = t[0]; bh[2 * p][1] = t[2];
                bh[2 * p + 1][0] = t[1]; bh[2 * p + 1][1] = t[3];
                ldm4(t, sb + 2 * TILE_B + rb);
                bl[2 * p][0] = t[0]; bl[2 * p][1] = t[2];
                bl[2 * p + 1][0] = t[1]; bl[2 * p + 1][1] = t[3];
            }
            #pragma unroll
            for (int mf = 0; mf < 2; mf++)
                #pragma unroll
                for (int nf = 0; nf < 4; nf++)
                    mma_f16(accm[mf][nf], ar[mf], bh[nf]);
            #pragma unroll
            for (int mf = 0; mf < 2; mf++)
                #pragma unroll
                for (int nf = 0; nf < 4; nf++)
                    mma_f16(accc[mf][nf], ar[mf], bl[nf]);
        }
    }

    const float inv2048 = 1.0f / 2048.0f;
    const int gid = lane >> 2;
    const int cq = (lane & 3) * 2;
    #pragma unroll
    for (int mf = 0; mf < 2; mf++) {
        const int row0 = m0 + wm * 32 + mf * 16 + gid;
        #pragma unroll
        for (int nf = 0; nf < 4; nf++) {
            const int col = n0 + wn * 32 + nf * 8 + cq;
            const float2 bv = *(const float2*)(bias + col);
            float2 v0, v1;
            v0.x = fmaf(accc[mf][nf][0], inv2048, accm[mf][nf][0]) + bv.x;
            v0.y = fmaf(accc[mf][nf][1], inv2048, accm[mf][nf][1]) + bv.y;
            v1.x = fmaf(accc[mf][nf][2], inv2048, accm[mf][nf][2]) + bv.x;
            v1.y = fmaf(accc[mf][nf][3], inv2048, accm[mf][nf][3]) + bv.y;
            if (act) {
                v0.x = (v0.x > 0.f) ? v0.x + 1.f : __expf(v0.x);
                v0.y = (v0.y > 0.f) ? v0.y + 1.f : __expf(v0.y);
                v1.x = (v1.x > 0.f) ? v1.x + 1.f : __expf(v1.x);
                v1.y = (v1.y > 0.f) ? v1.y + 1.f : __expf(v1.y);
            }
            *(float2*)(C + (size_t)row0 * DIM + col) = v0;
            *(float2*)(C + (size_t)(row0 + 8) * DIM + col) = v1;
        }
    }
}

// ---------------------------------------------------------------------------
__global__ __launch_bounds__(GTHREADS, 1)
void gemm_qkv_kernel(const float* __restrict__ bq,
                     const float* __restrict__ bk,
                     const float* __restrict__ bv)
{
    extern __shared__ __align__(16) char smem[];
    const int nb = blockIdx.x;
    const int mat = nb >> 3;
    const int n0 = (nb & 7) * GBN;
    const int m0 = blockIdx.y * GBM;

    const float* bias;
    float* C;
    int act;
    if (mat == 0)      { bias = bq; C = g_Q; act = 1; }
    else if (mat == 1) { bias = bk; C = g_K; act = 1; }
    else               { bias = bv; C = g_V; act = 0; }

    gemm_body(g_xh, g_wh[mat], g_wl[mat], bias, C, m0, n0, act, smem);
}

__global__ __launch_bounds__(GTHREADS, 1)
void gemm_o_kernel(const float* __restrict__ bias, float* __restrict__ C)
{
    extern __shared__ __align__(16) char smem[];
    gemm_body(g_ah, g_wh[3], g_wl[3], bias, C,
              blockIdx.y * GBM, blockIdx.x * GBN, 0, smem);
}

// ---------------------------------------------------------------------------
__global__ void zero_kv_kernel()
{
    const int i = blockIdx.x * 256 + threadIdx.x;
    if (i < BDIM * HEADS * HD * HD) g_KV[i] = 0.f;
    if (i < BDIM * HEADS * HD)      g_Ksum[i] = 0.f;
}

// ---------------------------------------------------------------------------
// KV[b,h,d,v] = sum_n K*V ; Ksum = sum_n K. f32x2 packed FMAs.
// ---------------------------------------------------------------------------
__global__ __launch_bounds__(256)
void kv_kernel(const float* __restrict__ K, const float* __restrict__ V)
{
    const int bh = blockIdx.x;
    const int seg = blockIdx.y;
    const int b = bh >> 4, h = bh & 15;
    const int tid = threadIdx.x;

    __shared__ __align__(16) float ks[8][64];
    __shared__ __align__(16) float vs[8][64];

    const int dq = tid >> 4;
    const int vq = tid & 15;
    unsigned long long acc2[4][2];
    #pragma unroll
    for (int a = 0; a < 4; a++) { acc2[a][0] = 0ull; acc2[a][1] = 0ull; }
    float ksacc = 0.f;

    const size_t base = ((size_t)b * NSEQ) * DIM + h * HD;
    const int row8 = tid >> 5;
    const int q = tid & 31;
    const bool isV = (q >= 16);
    const int c4 = (q & 15) * 4;

    const int nbeg = seg * (NSEQ / 8);
    const int nend = nbeg + (NSEQ / 8);

    for (int n0 = nbeg; n0 < nend; n0 += 8) {
        const size_t g = base + (size_t)(n0 + row8) * DIM + c4;
        float4 val = isV ? *(const float4*)(V + g) : *(const float4*)(K + g);
        float* dst = isV ? &vs[row8][c4] : &ks[row8][c4];
        *(float4*)dst = val;
        __syncthreads();
        #pragma unroll
        for (int i = 0; i < 8; i++) {
            const float4 kv = *(const float4*)&ks[i][dq * 4];
            const ulonglong2 vv = *(const ulonglong2*)&vs[i][vq * 4];
            unsigned long long k0 = pack2(kv.x), k1 = pack2(kv.y);
            unsigned long long k2 = pack2(kv.z), k3 = pack2(kv.w);
            ffma2(acc2[0][0], k0, vv.x); ffma2(acc2[0][1], k0, vv.y);
            ffma2(acc2[1][0], k1, vv.x); ffma2(acc2[1][1], k1, vv.y);
            ffma2(acc2[2][0], k2, vv.x); ffma2(acc2[2][1], k2, vv.y);
            ffma2(acc2[3][0], k3, vv.x); ffma2(acc2[3][1], k3, vv.y);
        }
        if (tid < 64) {
            #pragma unroll
            for (int i = 0; i < 8; i++) ksacc += ks[i][tid];
        }
        __syncthreads();
    }

    float* kvout = g_KV + bh * (HD * HD);
    #pragma unroll
    for (int a = 0; a < 4; a++) {
        float* row = &kvout[(dq * 4 + a) * HD + vq * 4];
        atomicAdd(row + 0, lo2(acc2[a][0]));
        atomicAdd(row + 1, hi2(acc2[a][0]));
        atomicAdd(row + 2, lo2(acc2[a][1]));
        atomicAdd(row + 3, hi2(acc2[a][1]));
    }
    if (tid < 64) atomicAdd(&g_Ksum[bh * HD + tid], ksacc);
}

// ---------------------------------------------------------------------------
// attn -> fp16 directly (consumed by gemm_o). f32x2 packed FMAs.
// ---------------------------------------------------------------------------
__global__ __launch_bounds__(256)
void attn_kernel(const float* __restrict__ Q,
                 const float* __restrict__ stdp,
                 __half* __restrict__ outh)
{
    const int bh = blockIdx.y;
    const int b = bh >> 4, h = bh & 15;
    const int n0 = blockIdx.x * 64;
    const int tid = threadIdx.x;

    __shared__ __align__(16) float qs[64][68];
    __shared__ __align__(16) float kvs[64][68];
    __shared__ float ksum_s[64];

    const size_t qbase = ((size_t)b * NSEQ + n0) * DIM + h * HD;
    #pragma unroll
    for (int i = 0; i < 4; i++) {
        const int slot = tid + i * 256;
        const int r = slot >> 4;
        const int c4 = (slot & 15) * 4;
        *(float4*)&qs[r][c4]  = *(const float4*)(Q + qbase + (size_t)r * DIM + c4);
        *(float4*)&kvs[r][c4] = *(const float4*)(g_KV + bh * (HD * HD) + r * HD + c4);
    }
    if (tid < 64) ksum_s[tid] = g_Ksum[bh * HD + tid];
    __syncthreads();

    const int r = tid >> 2;
    const int quad = tid & 3;
    unsigned long long acc2[8];
    #pragma unroll
    for (int j = 0; j < 8; j++) acc2[j] = 0ull;
    float den = 0.f;

    #pragma unroll 4
    for (int d = 0; d < 64; d++) {
        const float qv = qs[r][d];
        den += qv * ksum_s[d];
        const unsigned long long qp = pack2(qv);
        const ulonglong2 p0 = *(const ulonglong2*)&kvs[d][quad * 16 + 0];
        const ulonglong2 p1 = *(const ulonglong2*)&kvs[d][quad * 16 + 4];
        const ulonglong2 p2 = *(const ulonglong2*)&kvs[d][quad * 16 + 8];
        const ulonglong2 p3 = *(const ulonglong2*)&kvs[d][quad * 16 + 12];
        ffma2(acc2[0], qp, p0.x); ffma2(acc2[1], qp, p0.y);
        ffma2(acc2[2], qp, p1.x); ffma2(acc2[3], qp, p1.y);
        ffma2(acc2[4], qp, p2.x); ffma2(acc2[5], qp, p2.y);
        ffma2(acc2[6], qp, p3.x); ffma2(acc2[7], qp, p3.y);
    }

    const float sig = 1.f / (1.f + expf(-stdp[h]));
    const float scale = sig / (den + 1e-6f);

    const size_t obase = ((size_t)b * NSEQ + n0 + r) * DIM + h * HD + quad * 16;
    #pragma unroll
    for (int j = 0; j < 8; j++) {
        const unsigned long long v = acc2[j];
        *(__half2*)(outh + obase + j * 2) =
            __halves2half2(__float2half_rn(lo2(v) * scale),
                           __float2half_rn(hi2(v) * scale));
    }
}

// ---------------------------------------------------------------------------
__global__ void tail_kernel(const float* __restrict__ stdp,
                            float* __restrict__ out, int extra)
{
    const int i = threadIdx.x + blockIdx.x * blockDim.x;
    if (i < extra) {
        out[(size_t)MTOT * DIM + i] = (i < HEADS) ? stdp[i] : 0.f;
    }
}

// ---------------------------------------------------------------------------
extern "C" void kernel_launch(void* const* d_in, const int* in_sizes, int n_in,
                              void* d_out, int out_size)
{
    const float* x    = (const float*)d_in[0];
    const float* Wq   = (const float*)d_in[1];
    const float* bq   = (const float*)d_in[2];
    const float* Wk   = (const float*)d_in[3];
    const float* bk   = (const float*)d_in[4];
    const float* Wv   = (const float*)d_in[5];
    const float* bv   = (const float*)d_in[6];
    const float* Wo   = (const float*)d_in[7];
    const float* bo   = (const float*)d_in[8];
    const float* stdp = (const float*)d_in[9];
    float* out = (float*)d_out;

    float *pQ, *pK, *pV;
    cudaGetSymbolAddress((void**)&pQ, g_Q);
    cudaGetSymbolAddress((void**)&pK, g_K);
    cudaGetSymbolAddress((void**)&pV, g_V);
    __half* ah;
    cudaGetSymbolAddress((void**)&ah, g_ah);

    cudaFuncSetAttribute(gemm_qkv_kernel,
                         cudaFuncAttributeMaxDynamicSharedMemorySize, SMEMG);
    cudaFuncSetAttribute(gemm_o_kernel,
                         cudaFuncAttributeMaxDynamicSharedMemorySize, SMEMG);

    const int nx4 = MTOT * DIM / 4;

    // launch order: index 3 = gemm_qkv (ncu capture slot)
    wsplit_kernel<<<4096, 256>>>(Wq, Wk, Wv, Wo);                       // 0
    xconv_kernel<<<nx4 / 256, 256>>>(x);                                // 1
    zero_kv_kernel<<<(BDIM * HEADS * HD * HD + 255) / 256, 256>>>();    // 2
    gemm_qkv_kernel<<<dim3(24, MTOT / GBM), GTHREADS, SMEMG>>>(bq, bk, bv); // 3
    kv_kernel<<<dim3(BDIM * HEADS, 8), 256>>>(pK, pV);                  // 4
    attn_kernel<<<dim3(NSEQ / 64, BDIM * HEADS), 256>>>(pQ, stdp, ah);  // 5
    gemm_o_kernel<<<dim3(DIM / GBN, MTOT / GBM), GTHREADS, SMEMG>>>(bo, out); // 6

    const int extra = out_size - MTOT * DIM;
    if (extra > 0) {
        tail_kernel<<<(extra + 255) / 256, 256>>>(stdp, out, extra);    // 7
    }
}

// round 10
// speedup vs baseline: 4.1703x; 1.4450x over previous
#include <cuda_runtime.h>
#include <cuda_fp16.h>
#include <math.h>
#include <stdint.h>

// ---------------------------------------------------------------------------
// SpikeAttention (linear attention, ELU+1 feature map)
//   B=4, N=4096, DIM=1024, HEADS=16, HEAD_DIM=64
// Round 10: single-term fp16 GEMM (C = fp16(A) @ fp16(W)^T, fp32 accum).
// Error budget: activation+weight rounding ~1.4e-4 << 1e-3 gate.
// CTA tile 128x256, 512 threads, 16 warps (4Mx4N, 32x64 each), GBK=64, 4 stages.
// ---------------------------------------------------------------------------

#define BDIM  4
#define NSEQ  4096
#define DIM   1024
#define HEADS 16
#define HD    64
#define MTOT  (BDIM * NSEQ)          // 16384

__device__ float g_Q[(size_t)MTOT * DIM];
__device__ float g_K[(size_t)MTOT * DIM];
__device__ float g_V[(size_t)MTOT * DIM];
__device__ float g_KV[BDIM * HEADS * HD * HD];
__device__ float g_Ksum[BDIM * HEADS * HD];

__device__ __align__(16) __half g_xh[(size_t)MTOT * DIM];   // fp16(x)
__device__ __align__(16) __half g_ah[(size_t)MTOT * DIM];   // fp16(attn)
__device__ __align__(16) __half g_wh[4][DIM * DIM];          // fp16 weights

// ---- packed f32x2 helpers -------------------------------------------------
__device__ __forceinline__ unsigned long long pack2(float x) {
    unsigned long long r;
    unsigned u = __float_as_uint(x);
    asm("mov.b64 %0, {%1, %1};" : "=l"(r) : "r"(u));
    return r;
}
__device__ __forceinline__ void ffma2(unsigned long long& d,
                                      unsigned long long a,
                                      unsigned long long b) {
    asm("fma.rn.f32x2 %0, %1, %2, %0;" : "+l"(d) : "l"(a), "l"(b));
}
__device__ __forceinline__ float lo2(unsigned long long v) {
    return __uint_as_float((unsigned)(v & 0xffffffffull));
}
__device__ __forceinline__ float hi2(unsigned long long v) {
    return __uint_as_float((unsigned)(v >> 32));
}

// ---------------------------------------------------------------------------
// weight convert: fp32 -> fp16, all four matrices, grid.x = 4096
// ---------------------------------------------------------------------------
__global__ __launch_bounds__(256)
void wconv_kernel(const float* __restrict__ Wq, const float* __restrict__ Wk,
                  const float* __restrict__ Wv, const float* __restrict__ Wo)
{
    const int mat = blockIdx.x >> 10;
    const int i = (blockIdx.x & 1023) * 256 + threadIdx.x;
    const float* src = (mat == 0) ? Wq : (mat == 1) ? Wk : (mat == 2) ? Wv : Wo;
    float4 f = ((const float4*)src)[i];
    ((__half2*)g_wh[mat])[2 * i + 0] = __halves2half2(__float2half_rn(f.x),
                                                      __float2half_rn(f.y));
    ((__half2*)g_wh[mat])[2 * i + 1] = __halves2half2(__float2half_rn(f.z),
                                                      __float2half_rn(f.w));
}

__global__ __launch_bounds__(256)
void xconv_kernel(const float* __restrict__ x)
{
    const int i = blockIdx.x * 256 + threadIdx.x;
    float4 f = ((const float4*)x)[i];
    ((__half2*)g_xh)[2 * i + 0] = __halves2half2(__float2half_rn(f.x),
                                                 __float2half_rn(f.y));
    ((__half2*)g_xh)[2 * i + 1] = __halves2half2(__float2half_rn(f.z),
                                                 __float2half_rn(f.w));
}

// ===========================================================================
// GEMM core: 128x256 CTA tile, GBK=64, 4-stage cp.async, 512 threads,
// 16 warps (4 over M x 4 over N), each warp owns 32x64.
// ===========================================================================
#define GBM 128
#define GBN 256
#define GBK 64
#define NCHUNK (DIM / GBK)           // 16
#define RS 144
#define TILE_A (128 * RS)            // 18432
#define TILE_W (256 * RS)            // 36864
#define STAGE_B (TILE_A + TILE_W)    // 55296
#define GSTAGES 4
#define SMEMG (GSTAGES * STAGE_B)    // 221184
#define GTHREADS 512

__device__ __forceinline__ uint32_t smem_u32(const void* p) {
    uint32_t a;
    asm("{ .reg .u64 t; cvta.to.shared.u64 t, %1; cvt.u32.u64 %0, t; }"
        : "=r"(a) : "l"(p));
    return a;
}
__device__ __forceinline__ void cp16(uint32_t dst, const void* src) {
    asm volatile("cp.async.cg.shared.global [%0], [%1], 16;"
                 :: "r"(dst), "l"(src));
}
__device__ __forceinline__ void ldm4(uint32_t* r, uint32_t addr) {
    asm volatile("ldmatrix.sync.aligned.m8n8.x4.shared.b16 {%0,%1,%2,%3}, [%4];"
                 : "=r"(r[0]), "=r"(r[1]), "=r"(r[2]), "=r"(r[3]) : "r"(addr));
}
__device__ __forceinline__ void mma_f16(float* c, const uint32_t* a,
                                        const uint32_t* b) {
    asm volatile(
        "mma.sync.aligned.m16n8k16.row.col.f32.f16.f16.f32 "
        "{%0,%1,%2,%3}, {%4,%5,%6,%7}, {%8,%9}, {%0,%1,%2,%3};"
        : "+f"(c[0]), "+f"(c[1]), "+f"(c[2]), "+f"(c[3])
        : "r"(a[0]), "r"(a[1]), "r"(a[2]), "r"(a[3]), "r"(b[0]), "r"(b[1]));
}

__device__ __forceinline__
void gemm_body(const __half* __restrict__ A,
               const __half* __restrict__ W,
               const float* __restrict__ bias,
               float* __restrict__ C,
               int m0, int n0, int act, char* smem)
{
    const uint32_t sbase = smem_u32(smem);
    const int tid = threadIdx.x;
    const int lane = tid & 31;
    const int wid = tid >> 5;        // 0..15
    const int wm = wid & 3;          // 4 warps over M (32 rows)
    const int wn = wid >> 2;         // 4 warps over N (64 cols)

    // stage loader: 3072 x 16B granules (A:1024, W:2048), 6 per thread
    auto load_stage = [&](int ck, int slot) {
        const uint32_t sb = sbase + slot * STAGE_B;
        const int kofs = ck * GBK;
        #pragma unroll
        for (int i = 0; i < 6; i++) {
            const int id = tid + i * GTHREADS;   // 0..3071
            uint32_t dst;
            const __half* src;
            if (id < 1024) {                      // A: 128 rows x 8 granules
                const int r = id >> 3, c = id & 7;
                dst = sb + r * RS + c * 16;
                src = A + (size_t)(m0 + r) * DIM + kofs + c * 8;
            } else {                              // W: 256 rows x 8 granules
                const int id2 = id - 1024;
                const int r = id2 >> 3, c = id2 & 7;
                dst = sb + TILE_A + r * RS + c * 16;
                src = W + (size_t)(n0 + r) * DIM + kofs + c * 8;
            }
            cp16(dst, src);
        }
    };

    load_stage(0, 0);
    asm volatile("cp.async.commit_group;");
    load_stage(1, 1);
    asm volatile("cp.async.commit_group;");
    load_stage(2, 2);
    asm volatile("cp.async.commit_group;");

    float acc[2][8][4];
    #pragma unroll
    for (int mf = 0; mf < 2; mf++)
        #pragma unroll
        for (int nf = 0; nf < 8; nf++)
            #pragma unroll
            for (int e = 0; e < 4; e++) acc[mf][nf][e] = 0.f;

    const int rl = lane & 15;
    const int cb16 = (lane >> 4) << 4;

    for (int ck = 0; ck < NCHUNK; ck++) {
        asm volatile("cp.async.wait_group 2;");
        __syncthreads();
        if (ck + 3 < NCHUNK) load_stage(ck + 3, (ck + 3) & (GSTAGES - 1));
        asm volatile("cp.async.commit_group;");

        const uint32_t sb = sbase + (ck & (GSTAGES - 1)) * STAGE_B;
        #pragma unroll
        for (int k16 = 0; k16 < 4; k16++) {
            const int cb = k16 * 32 + cb16;
            uint32_t ar[2][4], bf[8][2];
            #pragma unroll
            for (int mf = 0; mf < 2; mf++) {
                const uint32_t ra = (wm * 32 + mf * 16 + rl) * RS + cb;
                ldm4(ar[mf], sb + ra);
            }
            #pragma unroll
            for (int p = 0; p < 4; p++) {
                const uint32_t rb = (wn * 64 + p * 16 + rl) * RS + cb;
                uint32_t t[4];
                ldm4(t, sb + TILE_A + rb);
                bf[2 * p][0] = t[0]; bf[2 * p][1] = t[2];
                bf[2 * p + 1][0] = t[1]; bf[2 * p + 1][1] = t[3];
            }
            #pragma unroll
            for (int mf = 0; mf < 2; mf++)
                #pragma unroll
                for (int nf = 0; nf < 8; nf++)
                    mma_f16(acc[mf][nf], ar[mf], bf[nf]);
        }
    }

    const int gid = lane >> 2;
    const int cq = (lane & 3) * 2;
    #pragma unroll
    for (int mf = 0; mf < 2; mf++) {
        const int row0 = m0 + wm * 32 + mf * 16 + gid;
        #pragma unroll
        for (int nf = 0; nf < 8; nf++) {
            const int col = n0 + wn * 64 + nf * 8 + cq;
            const float2 bv = *(const float2*)(bias + col);
            float2 v0, v1;
            v0.x = acc[mf][nf][0] + bv.x;
            v0.y = acc[mf][nf][1] + bv.y;
            v1.x = acc[mf][nf][2] + bv.x;
            v1.y = acc[mf][nf][3] + bv.y;
            if (act) {
                v0.x = (v0.x > 0.f) ? v0.x + 1.f : __expf(v0.x);
                v0.y = (v0.y > 0.f) ? v0.y + 1.f : __expf(v0.y);
                v1.x = (v1.x > 0.f) ? v1.x + 1.f : __expf(v1.x);
                v1.y = (v1.y > 0.f) ? v1.y + 1.f : __expf(v1.y);
            }
            *(float2*)(C + (size_t)row0 * DIM + col) = v0;
            *(float2*)(C + (size_t)(row0 + 8) * DIM + col) = v1;
        }
    }
}

// ---------------------------------------------------------------------------
// fused Q/K/V GEMM: grid.x in [0,12): matrix = x>>2, n-tile = x&3
// ---------------------------------------------------------------------------
__global__ __launch_bounds__(GTHREADS, 1)
void gemm_qkv_kernel(const float* __restrict__ bq,
                     const float* __restrict__ bk,
                     const float* __restrict__ bv)
{
    extern __shared__ __align__(16) char smem[];
    const int nb = blockIdx.x;
    const int mat = nb >> 2;
    const int n0 = (nb & 3) * GBN;
    const int m0 = blockIdx.y * GBM;

    const float* bias;
    float* C;
    int act;
    if (mat == 0)      { bias = bq; C = g_Q; act = 1; }
    else if (mat == 1) { bias = bk; C = g_K; act = 1; }
    else               { bias = bv; C = g_V; act = 0; }

    gemm_body(g_xh, g_wh[mat], bias, C, m0, n0, act, smem);
}

__global__ __launch_bounds__(GTHREADS, 1)
void gemm_o_kernel(const float* __restrict__ bias, float* __restrict__ C)
{
    extern __shared__ __align__(16) char smem[];
    gemm_body(g_ah, g_wh[3], bias, C,
              blockIdx.y * GBM, blockIdx.x * GBN, 0, smem);
}

// ---------------------------------------------------------------------------
__global__ void zero_kv_kernel()
{
    const int i = blockIdx.x * 256 + threadIdx.x;
    if (i < BDIM * HEADS * HD * HD) g_KV[i] = 0.f;
    if (i < BDIM * HEADS * HD)      g_Ksum[i] = 0.f;
}

// ---------------------------------------------------------------------------
// KV[b,h,d,v] = sum_n K*V ; Ksum = sum_n K. f32x2 packed FMAs.
// ---------------------------------------------------------------------------
__global__ __launch_bounds__(256)
void kv_kernel(const float* __restrict__ K, const float* __restrict__ V)
{
    const int bh = blockIdx.x;
    const int seg = blockIdx.y;
    const int b = bh >> 4, h = bh & 15;
    const int tid = threadIdx.x;

    __shared__ __align__(16) float ks[8][64];
    __shared__ __align__(16) float vs[8][64];

    const int dq = tid >> 4;
    const int vq = tid & 15;
    unsigned long long acc2[4][2];
    #pragma unroll
    for (int a = 0; a < 4; a++) { acc2[a][0] = 0ull; acc2[a][1] = 0ull; }
    float ksacc = 0.f;

    const size_t base = ((size_t)b * NSEQ) * DIM + h * HD;
    const int row8 = tid >> 5;
    const int q = tid & 31;
    const bool isV = (q >= 16);
    const int c4 = (q & 15) * 4;

    const int nbeg = seg * (NSEQ / 8);
    const int nend = nbeg + (NSEQ / 8);

    for (int n0 = nbeg; n0 < nend; n0 += 8) {
        const size_t g = base + (size_t)(n0 + row8) * DIM + c4;
        float4 val = isV ? *(const float4*)(V + g) : *(const float4*)(K + g);
        float* dst = isV ? &vs[row8][c4] : &ks[row8][c4];
        *(float4*)dst = val;
        __syncthreads();
        #pragma unroll
        for (int i = 0; i < 8; i++) {
            const float4 kv = *(const float4*)&ks[i][dq * 4];
            const ulonglong2 vv = *(const ulonglong2*)&vs[i][vq * 4];
            unsigned long long k0 = pack2(kv.x), k1 = pack2(kv.y);
            unsigned long long k2 = pack2(kv.z), k3 = pack2(kv.w);
            ffma2(acc2[0][0], k0, vv.x); ffma2(acc2[0][1], k0, vv.y);
            ffma2(acc2[1][0], k1, vv.x); ffma2(acc2[1][1], k1, vv.y);
            ffma2(acc2[2][0], k2, vv.x); ffma2(acc2[2][1], k2, vv.y);
            ffma2(acc2[3][0], k3, vv.x); ffma2(acc2[3][1], k3, vv.y);
        }
        if (tid < 64) {
            #pragma unroll
            for (int i = 0; i < 8; i++) ksacc += ks[i][tid];
        }
        __syncthreads();
    }

    float* kvout = g_KV + bh * (HD * HD);
    #pragma unroll
    for (int a = 0; a < 4; a++) {
        float* row = &kvout[(dq * 4 + a) * HD + vq * 4];
        atomicAdd(row + 0, lo2(acc2[a][0]));
        atomicAdd(row + 1, hi2(acc2[a][0]));
        atomicAdd(row + 2, lo2(acc2[a][1]));
        atomicAdd(row + 3, hi2(acc2[a][1]));
    }
    if (tid < 64) atomicAdd(&g_Ksum[bh * HD + tid], ksacc);
}

// ---------------------------------------------------------------------------
// attn -> fp16 directly (consumed by gemm_o). f32x2 packed FMAs.
// ---------------------------------------------------------------------------
__global__ __launch_bounds__(256)
void attn_kernel(const float* __restrict__ Q,
                 const float* __restrict__ stdp,
                 __half* __restrict__ outh)
{
    const int bh = blockIdx.y;
    const int b = bh >> 4, h = bh & 15;
    const int n0 = blockIdx.x * 64;
    const int tid = threadIdx.x;

    __shared__ __align__(16) float qs[64][68];
    __shared__ __align__(16) float kvs[64][68];
    __shared__ float ksum_s[64];

    const size_t qbase = ((size_t)b * NSEQ + n0) * DIM + h * HD;
    #pragma unroll
    for (int i = 0; i < 4; i++) {
        const int slot = tid + i * 256;
        const int r = slot >> 4;
        const int c4 = (slot & 15) * 4;
        *(float4*)&qs[r][c4]  = *(const float4*)(Q + qbase + (size_t)r * DIM + c4);
        *(float4*)&kvs[r][c4] = *(const float4*)(g_KV + bh * (HD * HD) + r * HD + c4);
    }
    if (tid < 64) ksum_s[tid] = g_Ksum[bh * HD + tid];
    __syncthreads();

    const int r = tid >> 2;
    const int quad = tid & 3;
    unsigned long long acc2[8];
    #pragma unroll
    for (int j = 0; j < 8; j++) acc2[j] = 0ull;
    float den = 0.f;

    #pragma unroll 4
    for (int d = 0; d < 64; d++) {
        const float qv = qs[r][d];
        den += qv * ksum_s[d];
        const unsigned long long qp = pack2(qv);
        const ulonglong2 p0 = *(const ulonglong2*)&kvs[d][quad * 16 + 0];
        const ulonglong2 p1 = *(const ulonglong2*)&kvs[d][quad * 16 + 4];
        const ulonglong2 p2 = *(const ulonglong2*)&kvs[d][quad * 16 + 8];
        const ulonglong2 p3 = *(const ulonglong2*)&kvs[d][quad * 16 + 12];
        ffma2(acc2[0], qp, p0.x); ffma2(acc2[1], qp, p0.y);
        ffma2(acc2[2], qp, p1.x); ffma2(acc2[3], qp, p1.y);
        ffma2(acc2[4], qp, p2.x); ffma2(acc2[5], qp, p2.y);
        ffma2(acc2[6], qp, p3.x); ffma2(acc2[7], qp, p3.y);
    }

    const float sig = 1.f / (1.f + expf(-stdp[h]));
    const float scale = sig / (den + 1e-6f);

    const size_t obase = ((size_t)b * NSEQ + n0 + r) * DIM + h * HD + quad * 16;
    #pragma unroll
    for (int j = 0; j < 8; j++) {
        const unsigned long long v = acc2[j];
        *(__half2*)(outh + obase + j * 2) =
            __halves2half2(__float2half_rn(lo2(v) * scale),
                           __float2half_rn(hi2(v) * scale));
    }
}

// ---------------------------------------------------------------------------
__global__ void tail_kernel(const float* __restrict__ stdp,
                            float* __restrict__ out, int extra)
{
    const int i = threadIdx.x + blockIdx.x * blockDim.x;
    if (i < extra) {
        out[(size_t)MTOT * DIM + i] = (i < HEADS) ? stdp[i] : 0.f;
    }
}

// ---------------------------------------------------------------------------
extern "C" void kernel_launch(void* const* d_in, const int* in_sizes, int n_in,
                              void* d_out, int out_size)
{
    const float* x    = (const float*)d_in[0];
    const float* Wq   = (const float*)d_in[1];
    const float* bq   = (const float*)d_in[2];
    const float* Wk   = (const float*)d_in[3];
    const float* bk   = (const float*)d_in[4];
    const float* Wv   = (const float*)d_in[5];
    const float* bv   = (const float*)d_in[6];
    const float* Wo   = (const float*)d_in[7];
    const float* bo   = (const float*)d_in[8];
    const float* stdp = (const float*)d_in[9];
    float* out = (float*)d_out;

    float *pQ, *pK, *pV;
    cudaGetSymbolAddress((void**)&pQ, g_Q);
    cudaGetSymbolAddress((void**)&pK, g_K);
    cudaGetSymbolAddress((void**)&pV, g_V);
    __half* ah;
    cudaGetSymbolAddress((void**)&ah, g_ah);

    cudaFuncSetAttribute(gemm_qkv_kernel,
                         cudaFuncAttributeMaxDynamicSharedMemorySize, SMEMG);
    cudaFuncSetAttribute(gemm_o_kernel,
                         cudaFuncAttributeMaxDynamicSharedMemorySize, SMEMG);

    const int nx4 = MTOT * DIM / 4;

    // launch order: index 3 = gemm_qkv (ncu capture slot)
    wconv_kernel<<<4096, 256>>>(Wq, Wk, Wv, Wo);                        // 0
    xconv_kernel<<<nx4 / 256, 256>>>(x);                                // 1
    zero_kv_kernel<<<(BDIM * HEADS * HD * HD + 255) / 256, 256>>>();    // 2
    gemm_qkv_kernel<<<dim3(12, MTOT / GBM), GTHREADS, SMEMG>>>(bq, bk, bv); // 3
    kv_kernel<<<dim3(BDIM * HEADS, 8), 256>>>(pK, pV);                  // 4
    attn_kernel<<<dim3(NSEQ / 64, BDIM * HEADS), 256>>>(pQ, stdp, ah);  // 5
    gemm_o_kernel<<<dim3(DIM / GBN, MTOT / GBM), GTHREADS, SMEMG>>>(bo, out); // 6

    const int extra = out_size - MTOT * DIM;
    if (extra > 0) {
        tail_kernel<<<(extra + 255) / 256, 256>>>(stdp, out, extra);    // 7
    }
}